// round 4
// baseline (speedup 1.0000x reference)
#include <cuda_runtime.h>
#include <cuda_bf16.h>
#include <cstdint>

#define NN 50000
#define NE 800000
#define ET 850000   // NE + NN self loops
#define D1 256      // heads(4) * h1(64)
#define D2 128

// ---------------- device scratch (static; no runtime allocation) ----------------
__device__ __align__(16) float g_xh1[NN * D1];   // X @ W1
__device__ __align__(16) float g_H1 [NN * D1];   // layer-1 output
__device__ __align__(16) float g_xh2[NN * D2];   // H1 @ W2
__device__ __align__(16) float g_as1[NN * 4];
__device__ __align__(16) float g_ad1[NN * 4];
__device__ float g_as2[NN];
__device__ float g_ad2[NN];
__device__ int g_deg[NN];
__device__ int g_rowptr[NN + 1];
__device__ int g_cursor[NN];
__device__ int g_eid[ET];
__device__ int g_bsum[64];
// transposed bf16 hi/lo weights: Wt[n][k]
__device__ __align__(16) __nv_bfloat16 g_wt1_hi[D1 * 64];
__device__ __align__(16) __nv_bfloat16 g_wt1_lo[D1 * 64];
__device__ __align__(16) __nv_bfloat16 g_wt2_hi[D2 * D1];
__device__ __align__(16) __nv_bfloat16 g_wt2_lo[D2 * D1];

__device__ __forceinline__ int esrc(const int* __restrict__ ei, int e) {
    return e < NE ? ei[e] : e - NE;
}
__device__ __forceinline__ int edst(const int* __restrict__ ei, int e) {
    return e < NE ? ei[NE + e] : e - NE;
}
__device__ __forceinline__ float lrelu(float x) { return x > 0.f ? x : 0.2f * x; }

// ---------------- CSR build ----------------
__global__ void k_zero_deg() {
    int i = blockIdx.x * 256 + threadIdx.x;
    if (i < NN) g_deg[i] = 0;
}

__global__ void k_count(const int* __restrict__ ei) {
    int e = blockIdx.x * 256 + threadIdx.x;
    if (e < ET) atomicAdd(&g_deg[edst(ei, e)], 1);
}

__global__ void k_scan1() {
    __shared__ int s[1024];
    int t = threadIdx.x;
    int i = blockIdx.x * 1024 + t;
    int v = (i < NN) ? g_deg[i] : 0;
    s[t] = v;
    __syncthreads();
    #pragma unroll
    for (int off = 1; off < 1024; off <<= 1) {
        int x = (t >= off) ? s[t - off] : 0;
        __syncthreads();
        s[t] += x;
        __syncthreads();
    }
    if (i < NN) g_rowptr[i] = s[t] - v;   // exclusive
    if (t == 1023) g_bsum[blockIdx.x] = s[t];
}

__global__ void k_scan2(int nblocks) {
    __shared__ int s[64];
    int t = threadIdx.x;
    int v = (t < nblocks) ? g_bsum[t] : 0;
    s[t] = v;
    __syncthreads();
    #pragma unroll
    for (int off = 1; off < 64; off <<= 1) {
        int x = (t >= off) ? s[t - off] : 0;
        __syncthreads();
        s[t] += x;
        __syncthreads();
    }
    if (t < nblocks) g_bsum[t] = s[t] - v;   // exclusive block offsets
}

__global__ void k_scan3() {
    int i = blockIdx.x * 1024 + threadIdx.x;
    if (i < NN) {
        int r = g_rowptr[i] + g_bsum[blockIdx.x];
        g_rowptr[i] = r;
        g_cursor[i] = r;
    }
    if (i == 0) g_rowptr[NN] = ET;
}

__global__ void k_fill(const int* __restrict__ ei) {
    int e = blockIdx.x * 256 + threadIdx.x;
    if (e < ET) {
        int d = edst(ei, e);
        int p = atomicAdd(&g_cursor[d], 1);
        g_eid[p] = e;
    }
}

// ---------------- weight transpose + bf16 hi/lo split ----------------
__global__ void k_prep_w1(const float* __restrict__ W1) {
    int idx = blockIdx.x * 256 + threadIdx.x;   // over 64*256
    if (idx >= 64 * D1) return;
    int k = idx / D1, n = idx % D1;
    float w = W1[idx];
    __nv_bfloat16 hi = __float2bfloat16(w);
    __nv_bfloat16 lo = __float2bfloat16(w - __bfloat162float(hi));
    g_wt1_hi[n * 64 + k] = hi;
    g_wt1_lo[n * 64 + k] = lo;
}
__global__ void k_prep_w2(const float* __restrict__ W2) {
    int idx = blockIdx.x * 256 + threadIdx.x;   // over 256*128
    if (idx >= D1 * D2) return;
    int k = idx / D2, n = idx % D2;
    float w = W2[idx];
    __nv_bfloat16 hi = __float2bfloat16(w);
    __nv_bfloat16 lo = __float2bfloat16(w - __bfloat162float(hi));
    g_wt2_hi[n * D1 + k] = hi;
    g_wt2_lo[n * D1 + k] = lo;
}

// ---------------- HMMA bf16 GEMM, 3-term compensation, single fill per chunk ----------------
// C[M, NCOL] = A[M, KTOT] @ Bt^T. Terms: Ah*Bh + Al*Bh + Ah*Bl over same SMEM chunk.
// Block tile 128x128, 8 warps (2x4) of 64x32, K-chunk 64, ldmatrix fragment loads.
#define KCH 64
#define ASTR 72   // padded row stride in bf16 (144B) -> conflict-free ldmatrix

__device__ __forceinline__ void ldsm4(uint32_t& r0, uint32_t& r1, uint32_t& r2, uint32_t& r3,
                                      const __nv_bfloat16* p) {
    uint32_t a = (uint32_t)__cvta_generic_to_shared(p);
    asm volatile("ldmatrix.sync.aligned.m8n8.x4.shared.b16 {%0,%1,%2,%3}, [%4];"
                 : "=r"(r0), "=r"(r1), "=r"(r2), "=r"(r3) : "r"(a));
}
__device__ __forceinline__ void mma16816(float* d, uint32_t a0, uint32_t a1, uint32_t a2,
                                         uint32_t a3, uint32_t b0, uint32_t b1) {
    asm volatile(
        "mma.sync.aligned.m16n8k16.row.col.f32.bf16.bf16.f32 "
        "{%0,%1,%2,%3}, {%4,%5,%6,%7}, {%8,%9}, {%0,%1,%2,%3};"
        : "+f"(d[0]), "+f"(d[1]), "+f"(d[2]), "+f"(d[3])
        : "r"(a0), "r"(a1), "r"(a2), "r"(a3), "r"(b0), "r"(b1));
}

template<int KTOT>
__global__ __launch_bounds__(256) void k_gemm_bf3(const float* __restrict__ A,
                                                  const __nv_bfloat16* __restrict__ BtHi,
                                                  const __nv_bfloat16* __restrict__ BtLo,
                                                  float* __restrict__ C,
                                                  int M, int NCOL) {
    extern __shared__ __align__(16) __nv_bfloat16 sm[];
    __nv_bfloat16* Ah = sm;                    // 128*ASTR
    __nv_bfloat16* Al = sm + 128 * ASTR;
    __nv_bfloat16* Bh = sm + 2 * 128 * ASTR;
    __nv_bfloat16* Bl = sm + 3 * 128 * ASTR;

    int tid = threadIdx.x;
    int wid = tid >> 5, lane = tid & 31;
    int g = lane >> 2, tig = lane & 3;
    int wm = (wid >> 2) * 64;    // warp M offset in block
    int wn = (wid & 3) * 32;     // warp N offset in block
    int bm = blockIdx.y * 128;
    int bn = blockIdx.x * 128;

    float acc[4][4][4];
    #pragma unroll
    for (int mt = 0; mt < 4; mt++)
        #pragma unroll
        for (int nt = 0; nt < 4; nt++)
            #pragma unroll
            for (int f = 0; f < 4; f++) acc[mt][nt][f] = 0.f;

    int arow = tid >> 1;
    int acs = (tid & 1) * 32;

    // ldmatrix lane addressing
    int a_r = lane & 15, a_c = (lane >> 4) * 8;                       // A frags
    int b_r = (lane >> 4) * 8 + (lane & 7), b_c = ((lane >> 3) & 1) * 8; // B frags (2 n-tiles)

    for (int kbase = 0; kbase < KTOT; kbase += KCH) {
        // ---- fill A hi+lo (each thread: 1/2 row, 32 cols = 8 float4) ----
        {
            bool valid = (bm + arow) < M;
            const float* src = A + (size_t)(bm + arow) * KTOT + kbase + acs;
            #pragma unroll
            for (int j = 0; j < 8; j++) {
                float4 v = valid ? *(const float4*)(src + 4 * j)
                                 : make_float4(0.f, 0.f, 0.f, 0.f);
                __nv_bfloat16 hx = __float2bfloat16(v.x), hy = __float2bfloat16(v.y);
                __nv_bfloat16 hz = __float2bfloat16(v.z), hw = __float2bfloat16(v.w);
                __nv_bfloat16 lx = __float2bfloat16(v.x - __bfloat162float(hx));
                __nv_bfloat16 ly = __float2bfloat16(v.y - __bfloat162float(hy));
                __nv_bfloat16 lz = __float2bfloat16(v.z - __bfloat162float(hz));
                __nv_bfloat16 lw = __float2bfloat16(v.w - __bfloat162float(hw));
                uint2 hp = make_uint2(
                    (uint32_t)__bfloat16_as_ushort(hx) | ((uint32_t)__bfloat16_as_ushort(hy) << 16),
                    (uint32_t)__bfloat16_as_ushort(hz) | ((uint32_t)__bfloat16_as_ushort(hw) << 16));
                uint2 lp = make_uint2(
                    (uint32_t)__bfloat16_as_ushort(lx) | ((uint32_t)__bfloat16_as_ushort(ly) << 16),
                    (uint32_t)__bfloat16_as_ushort(lz) | ((uint32_t)__bfloat16_as_ushort(lw) << 16));
                *(uint2*)&Ah[arow * ASTR + acs + 4 * j] = hp;
                *(uint2*)&Al[arow * ASTR + acs + 4 * j] = lp;
            }
        }
        // ---- fill B hi+lo (uint4 copies) ----
        #pragma unroll
        for (int j = 0; j < 4; j++) {
            int idx = tid + j * 256;           // 0..1023
            int row = idx >> 3;
            int col = (idx & 7) * 8;
            *(uint4*)&Bh[row * ASTR + col] =
                *(const uint4*)&BtHi[(size_t)(bn + row) * KTOT + kbase + col];
            *(uint4*)&Bl[row * ASTR + col] =
                *(const uint4*)&BtLo[(size_t)(bn + row) * KTOT + kbase + col];
        }
        __syncthreads();

        // ---- 4 k16 steps, 3 terms each over same SMEM ----
        #pragma unroll
        for (int ks = 0; ks < KCH; ks += 16) {
            uint32_t bh[4][2], bl[4][2];
            #pragma unroll
            for (int p = 0; p < 2; p++) {
                const __nv_bfloat16* pb = &Bh[(wn + p * 16 + b_r) * ASTR + ks + b_c];
                ldsm4(bh[2*p][0], bh[2*p][1], bh[2*p+1][0], bh[2*p+1][1], pb);
                const __nv_bfloat16* pl = &Bl[(wn + p * 16 + b_r) * ASTR + ks + b_c];
                ldsm4(bl[2*p][0], bl[2*p][1], bl[2*p+1][0], bl[2*p+1][1], pl);
            }
            #pragma unroll
            for (int mt = 0; mt < 4; mt++) {
                uint32_t ah0, ah1, ah2, ah3, al0, al1, al2, al3;
                ldsm4(ah0, ah1, ah2, ah3, &Ah[(wm + mt * 16 + a_r) * ASTR + ks + a_c]);
                ldsm4(al0, al1, al2, al3, &Al[(wm + mt * 16 + a_r) * ASTR + ks + a_c]);
                #pragma unroll
                for (int nt = 0; nt < 4; nt++)
                    mma16816(acc[mt][nt], ah0, ah1, ah2, ah3, bh[nt][0], bh[nt][1]);
                #pragma unroll
                for (int nt = 0; nt < 4; nt++)
                    mma16816(acc[mt][nt], al0, al1, al2, al3, bh[nt][0], bh[nt][1]);
                #pragma unroll
                for (int nt = 0; nt < 4; nt++)
                    mma16816(acc[mt][nt], ah0, ah1, ah2, ah3, bl[nt][0], bl[nt][1]);
            }
        }
        __syncthreads();
    }

    // ---- epilogue: direct fp32 stores ----
    #pragma unroll
    for (int mt = 0; mt < 4; mt++) {
        int r0 = bm + wm + mt * 16 + g;
        int r1 = r0 + 8;
        #pragma unroll
        for (int nt = 0; nt < 4; nt++) {
            int col = bn + wn + nt * 8 + 2 * tig;
            if (r0 < M)
                *(float2*)&C[(size_t)r0 * NCOL + col] = make_float2(acc[mt][nt][0], acc[mt][nt][1]);
            if (r1 < M)
                *(float2*)&C[(size_t)r1 * NCOL + col] = make_float2(acc[mt][nt][2], acc[mt][nt][3]);
        }
    }
}

// ---------------- attention logit vectors ----------------
__global__ __launch_bounds__(256) void k_attn1(const float* __restrict__ att_s,
                                               const float* __restrict__ att_d) {
    int w = (blockIdx.x * blockDim.x + threadIdx.x) >> 5;
    int lane = threadIdx.x & 31;
    if (w >= NN) return;
    const float4* xp = (const float4*)&g_xh1[(size_t)w * D1 + lane * 8];
    float4 x0 = xp[0], x1 = xp[1];
    const float4* ap = (const float4*)&att_s[lane * 8];
    float4 a0 = ap[0], a1 = ap[1];
    const float4* dp = (const float4*)&att_d[lane * 8];
    float4 d0 = dp[0], d1 = dp[1];
    float ss = x0.x*a0.x + x0.y*a0.y + x0.z*a0.z + x0.w*a0.w
             + x1.x*a1.x + x1.y*a1.y + x1.z*a1.z + x1.w*a1.w;
    float sd = x0.x*d0.x + x0.y*d0.y + x0.z*d0.z + x0.w*d0.w
             + x1.x*d1.x + x1.y*d1.y + x1.z*d1.z + x1.w*d1.w;
    #pragma unroll
    for (int m = 1; m < 8; m <<= 1) {
        ss += __shfl_xor_sync(0xffffffffu, ss, m);
        sd += __shfl_xor_sync(0xffffffffu, sd, m);
    }
    if ((lane & 7) == 0) {
        int h = lane >> 3;
        g_as1[w * 4 + h] = ss;
        g_ad1[w * 4 + h] = sd;
    }
}

__global__ __launch_bounds__(256) void k_attn2(const float* __restrict__ att_s,
                                               const float* __restrict__ att_d) {
    int w = (blockIdx.x * blockDim.x + threadIdx.x) >> 5;
    int lane = threadIdx.x & 31;
    if (w >= NN) return;
    float4 x = *(const float4*)&g_xh2[(size_t)w * D2 + lane * 4];
    float4 a = *(const float4*)&att_s[lane * 4];
    float4 d = *(const float4*)&att_d[lane * 4];
    float ss = x.x*a.x + x.y*a.y + x.z*a.z + x.w*a.w;
    float sd = x.x*d.x + x.y*d.y + x.z*d.z + x.w*d.w;
    #pragma unroll
    for (int m = 1; m < 32; m <<= 1) {
        ss += __shfl_xor_sync(0xffffffffu, ss, m);
        sd += __shfl_xor_sync(0xffffffffu, sd, m);
    }
    if (lane == 0) { g_as2[w] = ss; g_ad2[w] = sd; }
}

// ---------------- layer-1 aggregation: warp per destination node ----------------
__global__ __launch_bounds__(256) void k_agg1(const int* __restrict__ ei,
                                              const float* __restrict__ bias) {
    int w = (blockIdx.x * blockDim.x + threadIdx.x) >> 5;
    int lane = threadIdx.x & 31;
    if (w >= NN) return;
    int start = g_rowptr[w], end = g_rowptr[w + 1];
    float4 ad = *(const float4*)&g_ad1[w * 4];

    float s0 = 0.f, s1 = 0.f, s2 = 0.f, s3 = 0.f;
    for (int p = start + lane; p < end; p += 32) {
        int e = g_eid[p];
        int s = esrc(ei, e);
        float4 as = *(const float4*)&g_as1[s * 4];
        s0 += __expf(lrelu(as.x + ad.x));
        s1 += __expf(lrelu(as.y + ad.y));
        s2 += __expf(lrelu(as.z + ad.z));
        s3 += __expf(lrelu(as.w + ad.w));
    }
    #pragma unroll
    for (int m = 16; m >= 1; m >>= 1) {
        s0 += __shfl_xor_sync(0xffffffffu, s0, m);
        s1 += __shfl_xor_sync(0xffffffffu, s1, m);
        s2 += __shfl_xor_sync(0xffffffffu, s2, m);
        s3 += __shfl_xor_sync(0xffffffffu, s3, m);
    }

    int head = lane >> 3;
    float adh = (head == 0) ? ad.x : (head == 1) ? ad.y : (head == 2) ? ad.z : ad.w;
    float den = (head == 0) ? s0 : (head == 1) ? s1 : (head == 2) ? s2 : s3;
    float inv = 1.0f / den;
    float acc0 = 0.f, acc1 = 0.f, acc2 = 0.f, acc3 = 0.f;
    float acc4 = 0.f, acc5 = 0.f, acc6 = 0.f, acc7 = 0.f;
    for (int p = start; p < end; ++p) {
        int e = g_eid[p];
        int s = esrc(ei, e);
        float wgt = __expf(lrelu(g_as1[s * 4 + head] + adh)) * inv;
        const float4* xp = (const float4*)&g_xh1[(size_t)s * D1 + lane * 8];
        float4 v0 = xp[0], v1 = xp[1];
        acc0 += wgt * v0.x; acc1 += wgt * v0.y; acc2 += wgt * v0.z; acc3 += wgt * v0.w;
        acc4 += wgt * v1.x; acc5 += wgt * v1.y; acc6 += wgt * v1.z; acc7 += wgt * v1.w;
    }
    const float4* bp = (const float4*)&bias[lane * 8];
    float4 b0 = bp[0], b1v = bp[1];
    float4* op = (float4*)&g_H1[(size_t)w * D1 + lane * 8];
    op[0] = make_float4(acc0 + b0.x, acc1 + b0.y, acc2 + b0.z, acc3 + b0.w);
    op[1] = make_float4(acc4 + b1v.x, acc5 + b1v.y, acc6 + b1v.z, acc7 + b1v.w);
}

// ---------------- layer-2 aggregation (heads=1, C=128) ----------------
__global__ __launch_bounds__(256) void k_agg2(const int* __restrict__ ei,
                                              const float* __restrict__ bias,
                                              float* __restrict__ out) {
    int w = (blockIdx.x * blockDim.x + threadIdx.x) >> 5;
    int lane = threadIdx.x & 31;
    if (w >= NN) return;
    int start = g_rowptr[w], end = g_rowptr[w + 1];
    float ad = g_ad2[w];

    float se = 0.f;
    for (int p = start + lane; p < end; p += 32) {
        int e = g_eid[p];
        int s = esrc(ei, e);
        se += __expf(lrelu(g_as2[s] + ad));
    }
    #pragma unroll
    for (int m = 16; m >= 1; m >>= 1)
        se += __shfl_xor_sync(0xffffffffu, se, m);
    float inv = 1.0f / se;

    float acc0 = 0.f, acc1 = 0.f, acc2 = 0.f, acc3 = 0.f;
    for (int p = start; p < end; ++p) {
        int e = g_eid[p];
        int s = esrc(ei, e);
        float wgt = __expf(lrelu(g_as2[s] + ad)) * inv;
        float4 v = *(const float4*)&g_xh2[(size_t)s * D2 + lane * 4];
        acc0 += wgt * v.x; acc1 += wgt * v.y; acc2 += wgt * v.z; acc3 += wgt * v.w;
    }
    float4 b = *(const float4*)&bias[lane * 4];
    *(float4*)&out[(size_t)w * D2 + lane * 4] =
        make_float4(acc0 + b.x, acc1 + b.y, acc2 + b.z, acc3 + b.w);
}

// ---------------- host launch ----------------
extern "C" void kernel_launch(void* const* d_in, const int* in_sizes, int n_in,
                              void* d_out, int out_size) {
    const float* X    = (const float*)d_in[0];
    const int*   ei   = (const int*)  d_in[1];
    const float* W1   = (const float*)d_in[2];
    const float* as1  = (const float*)d_in[3];
    const float* ad1  = (const float*)d_in[4];
    const float* b1   = (const float*)d_in[5];
    const float* W2   = (const float*)d_in[6];
    const float* as2  = (const float*)d_in[7];
    const float* ad2  = (const float*)d_in[8];
    const float* b2   = (const float*)d_in[9];
    float* out = (float*)d_out;

    float *p_xh1, *p_H1, *p_xh2;
    cudaGetSymbolAddress((void**)&p_xh1, g_xh1);
    cudaGetSymbolAddress((void**)&p_H1,  g_H1);
    cudaGetSymbolAddress((void**)&p_xh2, g_xh2);
    __nv_bfloat16 *p_w1h, *p_w1l, *p_w2h, *p_w2l;
    cudaGetSymbolAddress((void**)&p_w1h, g_wt1_hi);
    cudaGetSymbolAddress((void**)&p_w1l, g_wt1_lo);
    cudaGetSymbolAddress((void**)&p_w2h, g_wt2_hi);
    cudaGetSymbolAddress((void**)&p_w2l, g_wt2_lo);

    const int SMEM_GEMM = 4 * 128 * ASTR * 2;   // 73728
    cudaFuncSetAttribute(k_gemm_bf3<64>, cudaFuncAttributeMaxDynamicSharedMemorySize, SMEM_GEMM);
    cudaFuncSetAttribute(k_gemm_bf3<D1>, cudaFuncAttributeMaxDynamicSharedMemorySize, SMEM_GEMM);

    const int SCAN_BLOCKS = (NN + 1023) / 1024;   // 49
    const int NODE_BLOCKS = (NN + 7) / 8;
    const int M_BLOCKS = (NN + 127) / 128;        // 391

    // Order chosen so the ncu-profiled launch slot lands on the layer-1 GEMM.
    k_zero_deg<<<(NN + 255) / 256, 256>>>();                                   // 0
    k_prep_w1<<<(64 * D1 + 255) / 256, 256>>>(W1);                             // 1
    k_prep_w2<<<(D1 * D2 + 255) / 256, 256>>>(W2);                             // 2
    k_gemm_bf3<64><<<dim3(D1 / 128, M_BLOCKS), 256, SMEM_GEMM>>>(X, p_w1h, p_w1l, p_xh1, NN, D1); // 3
    k_count<<<(ET + 255) / 256, 256>>>(ei);                                    // 4
    k_attn1<<<NODE_BLOCKS, 256>>>(as1, ad1);                                   // 5
    k_scan1<<<SCAN_BLOCKS, 1024>>>();                                          // 6
    k_scan2<<<1, 64>>>(SCAN_BLOCKS);                                           // 7
    k_scan3<<<SCAN_BLOCKS, 1024>>>();                                          // 8
    k_fill<<<(ET + 255) / 256, 256>>>(ei);                                     // 9
    k_agg1<<<NODE_BLOCKS, 256>>>(ei, b1);                                      // 10
    k_gemm_bf3<D1><<<dim3(D2 / 128, M_BLOCKS), 256, SMEM_GEMM>>>(p_H1, p_w2h, p_w2l, p_xh2, NN, D2); // 11
    k_attn2<<<NODE_BLOCKS, 256>>>(as2, ad2);                                   // 12
    k_agg2<<<NODE_BLOCKS, 256>>>(ei, b2, out);                                 // 13
}

// round 6
// speedup vs baseline: 1.2820x; 1.2820x over previous
#include <cuda_runtime.h>
#include <cuda_bf16.h>
#include <cstdint>

#define NN 50000
#define NE 800000
#define ET 850000   // NE + NN self loops
#define D1 256      // heads(4) * h1(64)
#define D2 128

// ---------------- device scratch (static; no runtime allocation) ----------------
__device__ __align__(16) float g_xh1[NN * D1];   // X @ W1
__device__ __align__(16) float g_H1 [NN * D1];   // layer-1 output
__device__ __align__(16) float g_xh2[NN * D2];   // H1 @ W2
__device__ __align__(16) float g_as1[NN * 4];
__device__ __align__(16) float g_ad1[NN * 4];
__device__ float g_as2[NN];
__device__ float g_ad2[NN];
__device__ int g_deg[NN];
__device__ int g_rowptr[NN + 1];
__device__ int g_cursor[NN];
__device__ int g_esrc[ET];      // CSR-position -> source node
__device__ int g_pdst[ET];      // CSR-position -> dest node
__device__ __align__(16) float g_w1[ET * 4];   // per-edge exp weights, layer 1 (4 heads)
__device__ float g_w2[ET];                     // per-edge exp weights, layer 2
__device__ int g_bsum[64];
// transposed bf16 hi/lo weights: Wt[n][k]
__device__ __align__(16) __nv_bfloat16 g_wt1_hi[D1 * 64];
__device__ __align__(16) __nv_bfloat16 g_wt1_lo[D1 * 64];
__device__ __align__(16) __nv_bfloat16 g_wt2_hi[D2 * D1];
__device__ __align__(16) __nv_bfloat16 g_wt2_lo[D2 * D1];

__device__ __forceinline__ int esrc_of(const int* __restrict__ ei, int e) {
    return e < NE ? ei[e] : e - NE;
}
__device__ __forceinline__ int edst_of(const int* __restrict__ ei, int e) {
    return e < NE ? ei[NE + e] : e - NE;
}
__device__ __forceinline__ float lrelu(float x) { return x > 0.f ? x : 0.2f * x; }

// ---------------- CSR build ----------------
__global__ void k_zero_deg() {
    int i = blockIdx.x * 256 + threadIdx.x;
    if (i < NN) g_deg[i] = 0;
}

__global__ void k_count(const int* __restrict__ ei) {
    int e = blockIdx.x * 256 + threadIdx.x;
    if (e < ET) atomicAdd(&g_deg[edst_of(ei, e)], 1);
}

__global__ void k_scan1() {
    __shared__ int s[1024];
    int t = threadIdx.x;
    int i = blockIdx.x * 1024 + t;
    int v = (i < NN) ? g_deg[i] : 0;
    s[t] = v;
    __syncthreads();
    #pragma unroll
    for (int off = 1; off < 1024; off <<= 1) {
        int x = (t >= off) ? s[t - off] : 0;
        __syncthreads();
        s[t] += x;
        __syncthreads();
    }
    if (i < NN) g_rowptr[i] = s[t] - v;   // exclusive
    if (t == 1023) g_bsum[blockIdx.x] = s[t];
}

__global__ void k_scan2(int nblocks) {
    __shared__ int s[64];
    int t = threadIdx.x;
    int v = (t < nblocks) ? g_bsum[t] : 0;
    s[t] = v;
    __syncthreads();
    #pragma unroll
    for (int off = 1; off < 64; off <<= 1) {
        int x = (t >= off) ? s[t - off] : 0;
        __syncthreads();
        s[t] += x;
        __syncthreads();
    }
    if (t < nblocks) g_bsum[t] = s[t] - v;   // exclusive block offsets
}

__global__ void k_scan3() {
    int i = blockIdx.x * 1024 + threadIdx.x;
    if (i < NN) {
        int r = g_rowptr[i] + g_bsum[blockIdx.x];
        g_rowptr[i] = r;
        g_cursor[i] = r;
    }
    if (i == 0) g_rowptr[NN] = ET;
}

__global__ void k_fill(const int* __restrict__ ei) {
    int e = blockIdx.x * 256 + threadIdx.x;
    if (e < ET) {
        int d = edst_of(ei, e);
        int s = esrc_of(ei, e);
        int p = atomicAdd(&g_cursor[d], 1);
        g_esrc[p] = s;
        g_pdst[p] = d;
    }
}

// ---------------- weight transpose + bf16 hi/lo split ----------------
__global__ void k_prep_w1(const float* __restrict__ W1) {
    int idx = blockIdx.x * 256 + threadIdx.x;   // over 64*256
    if (idx >= 64 * D1) return;
    int k = idx / D1, n = idx % D1;
    float w = W1[idx];
    __nv_bfloat16 hi = __float2bfloat16(w);
    __nv_bfloat16 lo = __float2bfloat16(w - __bfloat162float(hi));
    g_wt1_hi[n * 64 + k] = hi;
    g_wt1_lo[n * 64 + k] = lo;
}
__global__ void k_prep_w2(const float* __restrict__ W2) {
    int idx = blockIdx.x * 256 + threadIdx.x;   // over 256*128
    if (idx >= D1 * D2) return;
    int k = idx / D2, n = idx % D2;
    float w = W2[idx];
    __nv_bfloat16 hi = __float2bfloat16(w);
    __nv_bfloat16 lo = __float2bfloat16(w - __bfloat162float(hi));
    g_wt2_hi[n * D1 + k] = hi;
    g_wt2_lo[n * D1 + k] = lo;
}

// ---------------- HMMA bf16 GEMM with 3-term compensation (R3 version) ----------------
// C[M, NCOL] = A[M, KTOT] @ Bt^T, Bt[n][k] bf16 hi/lo. Extended K' = 3*KTOT:
//   segment t=0: A_hi * B_hi ; t=1: A_lo * B_hi ; t=2: A_hi * B_lo
// Block tile 128x128, 8 warps (2x4) of 64x32, K-chunk 32, mma.m16n8k16.
#define KC 32
#define ASTR 40   // padded SMEM row stride in bf16 (80B, 16B-aligned, conflict-free)

template<int KTOT>
__global__ __launch_bounds__(256) void k_gemm_bf3(const float* __restrict__ A,
                                                  const __nv_bfloat16* __restrict__ BtHi,
                                                  const __nv_bfloat16* __restrict__ BtLo,
                                                  float* __restrict__ C,
                                                  int M, int NCOL) {
    __shared__ __nv_bfloat16 As[128 * ASTR];
    __shared__ __nv_bfloat16 Bs[128 * ASTR];

    int tid = threadIdx.x;
    int wid = tid >> 5, lane = tid & 31;
    int g = lane >> 2, tig = lane & 3;
    int wm = (wid >> 2) * 64;    // warp M offset in block
    int wn = (wid & 3) * 32;     // warp N offset in block
    int bm = blockIdx.y * 128;
    int bn = blockIdx.x * 128;

    float acc[4][4][4];
    #pragma unroll
    for (int mt = 0; mt < 4; mt++)
        #pragma unroll
        for (int nt = 0; nt < 4; nt++)
            #pragma unroll
            for (int f = 0; f < 4; f++) acc[mt][nt][f] = 0.f;

    // A fill indexing: 2 threads per row, 16 cols each
    int arow = tid >> 1;
    int acs = (tid & 1) * 16;

    for (int kc0 = 0; kc0 < 3 * KTOT; kc0 += KC) {
        int t = kc0 / KTOT;
        int kbase = kc0 % KTOT;

        // ---- fill A (fp32 -> bf16 hi or lo) ----
        {
            bool valid = (bm + arow) < M;
            const float* src = A + (size_t)(bm + arow) * KTOT + kbase + acs;
            #pragma unroll
            for (int j = 0; j < 4; j++) {
                float4 v = valid ? *(const float4*)(src + 4 * j)
                                 : make_float4(0.f, 0.f, 0.f, 0.f);
                uint32_t p0, p1;
                if (t == 1) {
                    __nv_bfloat16 hx = __float2bfloat16(v.x), hy = __float2bfloat16(v.y);
                    __nv_bfloat16 hz = __float2bfloat16(v.z), hw = __float2bfloat16(v.w);
                    __nv_bfloat16 lx = __float2bfloat16(v.x - __bfloat162float(hx));
                    __nv_bfloat16 ly = __float2bfloat16(v.y - __bfloat162float(hy));
                    __nv_bfloat16 lz = __float2bfloat16(v.z - __bfloat162float(hz));
                    __nv_bfloat16 lw = __float2bfloat16(v.w - __bfloat162float(hw));
                    p0 = (uint32_t)__bfloat16_as_ushort(lx) | ((uint32_t)__bfloat16_as_ushort(ly) << 16);
                    p1 = (uint32_t)__bfloat16_as_ushort(lz) | ((uint32_t)__bfloat16_as_ushort(lw) << 16);
                } else {
                    __nv_bfloat16 hx = __float2bfloat16(v.x), hy = __float2bfloat16(v.y);
                    __nv_bfloat16 hz = __float2bfloat16(v.z), hw = __float2bfloat16(v.w);
                    p0 = (uint32_t)__bfloat16_as_ushort(hx) | ((uint32_t)__bfloat16_as_ushort(hy) << 16);
                    p1 = (uint32_t)__bfloat16_as_ushort(hz) | ((uint32_t)__bfloat16_as_ushort(hw) << 16);
                }
                uint2 pk = make_uint2(p0, p1);
                *(uint2*)&As[arow * ASTR + acs + 4 * j] = pk;
            }
        }
        // ---- fill B (bf16 copy, choose hi/lo array) ----
        {
            const __nv_bfloat16* Bsrc = (t == 2) ? BtLo : BtHi;
            #pragma unroll
            for (int r = 0; r < 2; r++) {
                int idx = tid + r * 256;          // 512 x uint4
                int row = idx >> 2;
                int part = (idx & 3) * 8;         // bf16 col offset
                uint4 v = *(const uint4*)&Bsrc[(size_t)(bn + row) * KTOT + kbase + part];
                *(uint4*)&Bs[row * ASTR + part] = v;
            }
        }
        __syncthreads();

        // ---- mma over 2 k16 steps ----
        #pragma unroll
        for (int ks = 0; ks < KC; ks += 16) {
            uint32_t bfr[4][2];
            #pragma unroll
            for (int nt = 0; nt < 4; nt++) {
                int n = wn + nt * 8 + g;
                bfr[nt][0] = *(const uint32_t*)&Bs[n * ASTR + ks + 2 * tig];
                bfr[nt][1] = *(const uint32_t*)&Bs[n * ASTR + ks + 2 * tig + 8];
            }
            #pragma unroll
            for (int mt = 0; mt < 4; mt++) {
                int r0 = wm + mt * 16 + g;
                uint32_t a0 = *(const uint32_t*)&As[r0 * ASTR + ks + 2 * tig];
                uint32_t a1 = *(const uint32_t*)&As[(r0 + 8) * ASTR + ks + 2 * tig];
                uint32_t a2 = *(const uint32_t*)&As[r0 * ASTR + ks + 2 * tig + 8];
                uint32_t a3 = *(const uint32_t*)&As[(r0 + 8) * ASTR + ks + 2 * tig + 8];
                #pragma unroll
                for (int nt = 0; nt < 4; nt++) {
                    asm volatile(
                        "mma.sync.aligned.m16n8k16.row.col.f32.bf16.bf16.f32 "
                        "{%0,%1,%2,%3}, {%4,%5,%6,%7}, {%8,%9}, {%0,%1,%2,%3};"
                        : "+f"(acc[mt][nt][0]), "+f"(acc[mt][nt][1]),
                          "+f"(acc[mt][nt][2]), "+f"(acc[mt][nt][3])
                        : "r"(a0), "r"(a1), "r"(a2), "r"(a3),
                          "r"(bfr[nt][0]), "r"(bfr[nt][1]));
                }
            }
        }
        __syncthreads();
    }

    // ---- epilogue: direct fp32 stores (float2 per fragment half) ----
    #pragma unroll
    for (int mt = 0; mt < 4; mt++) {
        int r0 = bm + wm + mt * 16 + g;
        int r1 = r0 + 8;
        #pragma unroll
        for (int nt = 0; nt < 4; nt++) {
            int col = bn + wn + nt * 8 + 2 * tig;
            if (r0 < M)
                *(float2*)&C[(size_t)r0 * NCOL + col] = make_float2(acc[mt][nt][0], acc[mt][nt][1]);
            if (r1 < M)
                *(float2*)&C[(size_t)r1 * NCOL + col] = make_float2(acc[mt][nt][2], acc[mt][nt][3]);
        }
    }
}

// ---------------- attention logit vectors ----------------
__global__ __launch_bounds__(256) void k_attn1(const float* __restrict__ att_s,
                                               const float* __restrict__ att_d) {
    int w = (blockIdx.x * blockDim.x + threadIdx.x) >> 5;
    int lane = threadIdx.x & 31;
    if (w >= NN) return;
    const float4* xp = (const float4*)&g_xh1[(size_t)w * D1 + lane * 8];
    float4 x0 = xp[0], x1 = xp[1];
    const float4* ap = (const float4*)&att_s[lane * 8];
    float4 a0 = ap[0], a1 = ap[1];
    const float4* dp = (const float4*)&att_d[lane * 8];
    float4 d0 = dp[0], d1 = dp[1];
    float ss = x0.x*a0.x + x0.y*a0.y + x0.z*a0.z + x0.w*a0.w
             + x1.x*a1.x + x1.y*a1.y + x1.z*a1.z + x1.w*a1.w;
    float sd = x0.x*d0.x + x0.y*d0.y + x0.z*d0.z + x0.w*d0.w
             + x1.x*d1.x + x1.y*d1.y + x1.z*d1.z + x1.w*d1.w;
    #pragma unroll
    for (int m = 1; m < 8; m <<= 1) {
        ss += __shfl_xor_sync(0xffffffffu, ss, m);
        sd += __shfl_xor_sync(0xffffffffu, sd, m);
    }
    if ((lane & 7) == 0) {
        int h = lane >> 3;
        g_as1[w * 4 + h] = ss;
        g_ad1[w * 4 + h] = sd;
    }
}

__global__ __launch_bounds__(256) void k_attn2(const float* __restrict__ att_s,
                                               const float* __restrict__ att_d) {
    int w = (blockIdx.x * blockDim.x + threadIdx.x) >> 5;
    int lane = threadIdx.x & 31;
    if (w >= NN) return;
    float4 x = *(const float4*)&g_xh2[(size_t)w * D2 + lane * 4];
    float4 a = *(const float4*)&att_s[lane * 4];
    float4 d = *(const float4*)&att_d[lane * 4];
    float ss = x.x*a.x + x.y*a.y + x.z*a.z + x.w*a.w;
    float sd = x.x*d.x + x.y*d.y + x.z*d.z + x.w*d.w;
    #pragma unroll
    for (int m = 1; m < 32; m <<= 1) {
        ss += __shfl_xor_sync(0xffffffffu, ss, m);
        sd += __shfl_xor_sync(0xffffffffu, sd, m);
    }
    if (lane == 0) { g_as2[w] = ss; g_ad2[w] = sd; }
}

// ---------------- per-edge exp weights (edge-parallel, CSR position order) ----------------
__global__ __launch_bounds__(256) void k_edgew1() {
    int p = blockIdx.x * 256 + threadIdx.x;
    if (p >= ET) return;
    int s = g_esrc[p];
    int d = g_pdst[p];
    float4 as = *(const float4*)&g_as1[s * 4];
    float4 ad = *(const float4*)&g_ad1[d * 4];
    float4 w;
    w.x = __expf(lrelu(as.x + ad.x));
    w.y = __expf(lrelu(as.y + ad.y));
    w.z = __expf(lrelu(as.z + ad.z));
    w.w = __expf(lrelu(as.w + ad.w));
    *(float4*)&g_w1[p * 4] = w;
}

__global__ __launch_bounds__(256) void k_edgew2() {
    int p = blockIdx.x * 256 + threadIdx.x;
    if (p >= ET) return;
    int s = g_esrc[p];
    int d = g_pdst[p];
    g_w2[p] = __expf(lrelu(g_as2[s] + g_ad2[d]));
}

// ---------------- layer-1 aggregation: warp per destination node ----------------
__global__ __launch_bounds__(256) void k_agg1(const float* __restrict__ bias) {
    int w = (blockIdx.x * blockDim.x + threadIdx.x) >> 5;
    int lane = threadIdx.x & 31;
    if (w >= NN) return;
    int start = g_rowptr[w], end = g_rowptr[w + 1];

    // pass A: softmax denominators = contiguous float4 sum
    float s0 = 0.f, s1 = 0.f, s2 = 0.f, s3 = 0.f;
    for (int p = start + lane; p < end; p += 32) {
        float4 wv = *(const float4*)&g_w1[p * 4];
        s0 += wv.x; s1 += wv.y; s2 += wv.z; s3 += wv.w;
    }
    #pragma unroll
    for (int m = 16; m >= 1; m >>= 1) {
        s0 += __shfl_xor_sync(0xffffffffu, s0, m);
        s1 += __shfl_xor_sync(0xffffffffu, s1, m);
        s2 += __shfl_xor_sync(0xffffffffu, s2, m);
        s3 += __shfl_xor_sync(0xffffffffu, s3, m);
    }

    int head = lane >> 3;
    float den = (head == 0) ? s0 : (head == 1) ? s1 : (head == 2) ? s2 : s3;
    float inv = 1.0f / den;

    // pass B: weighted gather, 2-edge software pipeline for MLP
    float acc0 = 0.f, acc1 = 0.f, acc2 = 0.f, acc3 = 0.f;
    float acc4 = 0.f, acc5 = 0.f, acc6 = 0.f, acc7 = 0.f;
    int p = start;
    for (; p + 1 < end; p += 2) {
        int sA = g_esrc[p];
        int sB = g_esrc[p + 1];
        float4 wA = *(const float4*)&g_w1[p * 4];
        float4 wB = *(const float4*)&g_w1[(p + 1) * 4];
        const float4* xa = (const float4*)&g_xh1[(size_t)sA * D1 + lane * 8];
        const float4* xb = (const float4*)&g_xh1[(size_t)sB * D1 + lane * 8];
        float4 a0 = xa[0], a1 = xa[1];
        float4 b0 = xb[0], b1 = xb[1];
        float gA = ((head == 0) ? wA.x : (head == 1) ? wA.y : (head == 2) ? wA.z : wA.w) * inv;
        float gB = ((head == 0) ? wB.x : (head == 1) ? wB.y : (head == 2) ? wB.z : wB.w) * inv;
        acc0 += gA * a0.x + gB * b0.x; acc1 += gA * a0.y + gB * b0.y;
        acc2 += gA * a0.z + gB * b0.z; acc3 += gA * a0.w + gB * b0.w;
        acc4 += gA * a1.x + gB * b1.x; acc5 += gA * a1.y + gB * b1.y;
        acc6 += gA * a1.z + gB * b1.z; acc7 += gA * a1.w + gB * b1.w;
    }
    if (p < end) {
        int sA = g_esrc[p];
        float4 wA = *(const float4*)&g_w1[p * 4];
        const float4* xa = (const float4*)&g_xh1[(size_t)sA * D1 + lane * 8];
        float4 a0 = xa[0], a1 = xa[1];
        float gA = ((head == 0) ? wA.x : (head == 1) ? wA.y : (head == 2) ? wA.z : wA.w) * inv;
        acc0 += gA * a0.x; acc1 += gA * a0.y; acc2 += gA * a0.z; acc3 += gA * a0.w;
        acc4 += gA * a1.x; acc5 += gA * a1.y; acc6 += gA * a1.z; acc7 += gA * a1.w;
    }
    const float4* bp = (const float4*)&bias[lane * 8];
    float4 b0 = bp[0], b1v = bp[1];
    float4* op = (float4*)&g_H1[(size_t)w * D1 + lane * 8];
    op[0] = make_float4(acc0 + b0.x, acc1 + b0.y, acc2 + b0.z, acc3 + b0.w);
    op[1] = make_float4(acc4 + b1v.x, acc5 + b1v.y, acc6 + b1v.z, acc7 + b1v.w);
}

// ---------------- layer-2 aggregation (heads=1, C=128) ----------------
__global__ __launch_bounds__(256) void k_agg2(const float* __restrict__ bias,
                                              float* __restrict__ out) {
    int w = (blockIdx.x * blockDim.x + threadIdx.x) >> 5;
    int lane = threadIdx.x & 31;
    if (w >= NN) return;
    int start = g_rowptr[w], end = g_rowptr[w + 1];

    float se = 0.f;
    for (int p = start + lane; p < end; p += 32)
        se += g_w2[p];
    #pragma unroll
    for (int m = 16; m >= 1; m >>= 1)
        se += __shfl_xor_sync(0xffffffffu, se, m);
    float inv = 1.0f / se;

    float acc0 = 0.f, acc1 = 0.f, acc2 = 0.f, acc3 = 0.f;
    int p = start;
    for (; p + 1 < end; p += 2) {
        int sA = g_esrc[p];
        int sB = g_esrc[p + 1];
        float gA = g_w2[p] * inv;
        float gB = g_w2[p + 1] * inv;
        float4 va = *(const float4*)&g_xh2[(size_t)sA * D2 + lane * 4];
        float4 vb = *(const float4*)&g_xh2[(size_t)sB * D2 + lane * 4];
        acc0 += gA * va.x + gB * vb.x; acc1 += gA * va.y + gB * vb.y;
        acc2 += gA * va.z + gB * vb.z; acc3 += gA * va.w + gB * vb.w;
    }
    if (p < end) {
        int sA = g_esrc[p];
        float gA = g_w2[p] * inv;
        float4 va = *(const float4*)&g_xh2[(size_t)sA * D2 + lane * 4];
        acc0 += gA * va.x; acc1 += gA * va.y; acc2 += gA * va.z; acc3 += gA * va.w;
    }
    float4 b = *(const float4*)&bias[lane * 4];
    *(float4*)&out[(size_t)w * D2 + lane * 4] =
        make_float4(acc0 + b.x, acc1 + b.y, acc2 + b.z, acc3 + b.w);
}

// ---------------- host launch ----------------
extern "C" void kernel_launch(void* const* d_in, const int* in_sizes, int n_in,
                              void* d_out, int out_size) {
    const float* X    = (const float*)d_in[0];
    const int*   ei   = (const int*)  d_in[1];
    const float* W1   = (const float*)d_in[2];
    const float* as1  = (const float*)d_in[3];
    const float* ad1  = (const float*)d_in[4];
    const float* b1   = (const float*)d_in[5];
    const float* W2   = (const float*)d_in[6];
    const float* as2  = (const float*)d_in[7];
    const float* ad2  = (const float*)d_in[8];
    const float* b2   = (const float*)d_in[9];
    float* out = (float*)d_out;

    float *p_xh1, *p_H1, *p_xh2;
    cudaGetSymbolAddress((void**)&p_xh1, g_xh1);
    cudaGetSymbolAddress((void**)&p_H1,  g_H1);
    cudaGetSymbolAddress((void**)&p_xh2, g_xh2);
    __nv_bfloat16 *p_w1h, *p_w1l, *p_w2h, *p_w2l;
    cudaGetSymbolAddress((void**)&p_w1h, g_wt1_hi);
    cudaGetSymbolAddress((void**)&p_w1l, g_wt1_lo);
    cudaGetSymbolAddress((void**)&p_w2h, g_wt2_hi);
    cudaGetSymbolAddress((void**)&p_w2l, g_wt2_lo);

    const int SCAN_BLOCKS = (NN + 1023) / 1024;   // 49
    const int NODE_BLOCKS = (NN + 7) / 8;
    const int M_BLOCKS = (NN + 127) / 128;        // 391
    const int EDGE_BLOCKS = (ET + 255) / 256;

    // slot 3 = layer-1 GEMM (ncu-profiled launch)
    k_zero_deg<<<(NN + 255) / 256, 256>>>();                                   // 0
    k_prep_w1<<<(64 * D1 + 255) / 256, 256>>>(W1);                             // 1
    k_prep_w2<<<(D1 * D2 + 255) / 256, 256>>>(W2);                             // 2
    k_gemm_bf3<64><<<dim3(D1 / 128, M_BLOCKS), 256>>>(X, p_w1h, p_w1l, p_xh1, NN, D1); // 3
    k_count<<<EDGE_BLOCKS, 256>>>(ei);                                         // 4
    k_scan1<<<SCAN_BLOCKS, 1024>>>();                                          // 5
    k_scan2<<<1, 64>>>(SCAN_BLOCKS);                                           // 6
    k_scan3<<<SCAN_BLOCKS, 1024>>>();                                          // 7
    k_fill<<<EDGE_BLOCKS, 256>>>(ei);                                          // 8
    k_attn1<<<NODE_BLOCKS, 256>>>(as1, ad1);                                   // 9
    k_edgew1<<<EDGE_BLOCKS, 256>>>();                                          // 10
    k_agg1<<<NODE_BLOCKS, 256>>>(b1);                                          // 11
    k_gemm_bf3<D1><<<dim3(D2 / 128, M_BLOCKS), 256>>>(p_H1, p_w2h, p_w2l, p_xh2, NN, D2); // 12
    k_attn2<<<NODE_BLOCKS, 256>>>(as2, ad2);                                   // 13
    k_edgew2<<<EDGE_BLOCKS, 256>>>();                                          // 14
    k_agg2<<<NODE_BLOCKS, 256>>>(b2, out);                                     // 15
}

// round 7
// speedup vs baseline: 1.7500x; 1.3650x over previous
#include <cuda_runtime.h>
#include <cuda_bf16.h>
#include <cstdint>

#define NN 50000
#define NE 800000
#define ET 850000   // NE + NN self loops
#define D1 256      // heads(4) * h1(64)
#define D2 128

// ---------------- device scratch (static; no runtime allocation) ----------------
__device__ __align__(16) float g_xh1[NN * D1];   // X @ W1 (fp32, for attn1 + agg1 gather)
__device__ __align__(16) float g_xh2[NN * D2];   // H1 @ W2 (fp32, for attn2 + agg2 gather)
__device__ __align__(16) __nv_bfloat16 g_x_hi[NN * 64];   // X split
__device__ __align__(16) __nv_bfloat16 g_x_lo[NN * 64];
__device__ __align__(16) __nv_bfloat16 g_h1_hi[NN * D1];  // H1 split (gemm2 A operand)
__device__ __align__(16) __nv_bfloat16 g_h1_lo[NN * D1];
__device__ __align__(16) float g_as1[NN * 4];
__device__ __align__(16) float g_ad1[NN * 4];
__device__ float g_as2[NN];
__device__ float g_ad2[NN];
__device__ int g_deg[NN];
__device__ int g_rowptr[NN + 1];
__device__ int g_cursor[NN];
__device__ int g_esrc[ET];      // CSR-position -> source node
__device__ __align__(16) float g_w1[ET * 4];   // per-edge exp weights, layer 1 (4 heads)
__device__ float g_w2[ET];                     // per-edge exp weights, layer 2
__device__ int g_bsum[64];
// transposed bf16 hi/lo weights: Wt[n][k]
__device__ __align__(16) __nv_bfloat16 g_wt1_hi[D1 * 64];
__device__ __align__(16) __nv_bfloat16 g_wt1_lo[D1 * 64];
__device__ __align__(16) __nv_bfloat16 g_wt2_hi[D2 * D1];
__device__ __align__(16) __nv_bfloat16 g_wt2_lo[D2 * D1];

__device__ __forceinline__ int esrc_of(const int* __restrict__ ei, int e) {
    return e < NE ? ei[e] : e - NE;
}
__device__ __forceinline__ int edst_of(const int* __restrict__ ei, int e) {
    return e < NE ? ei[NE + e] : e - NE;
}
__device__ __forceinline__ float lrelu(float x) { return x > 0.f ? x : 0.2f * x; }

// ---------------- CSR build ----------------
__global__ void k_zero_deg() {
    int i = blockIdx.x * 256 + threadIdx.x;
    if (i < NN) g_deg[i] = 0;
}

__global__ void k_count(const int* __restrict__ ei) {
    int e = blockIdx.x * 256 + threadIdx.x;
    if (e < ET) atomicAdd(&g_deg[edst_of(ei, e)], 1);
}

__global__ void k_scan1() {
    __shared__ int s[1024];
    int t = threadIdx.x;
    int i = blockIdx.x * 1024 + t;
    int v = (i < NN) ? g_deg[i] : 0;
    s[t] = v;
    __syncthreads();
    #pragma unroll
    for (int off = 1; off < 1024; off <<= 1) {
        int x = (t >= off) ? s[t - off] : 0;
        __syncthreads();
        s[t] += x;
        __syncthreads();
    }
    if (i < NN) g_rowptr[i] = s[t] - v;   // exclusive
    if (t == 1023) g_bsum[blockIdx.x] = s[t];
}

__global__ void k_scan2(int nblocks) {
    __shared__ int s[64];
    int t = threadIdx.x;
    int v = (t < nblocks) ? g_bsum[t] : 0;
    s[t] = v;
    __syncthreads();
    #pragma unroll
    for (int off = 1; off < 64; off <<= 1) {
        int x = (t >= off) ? s[t - off] : 0;
        __syncthreads();
        s[t] += x;
        __syncthreads();
    }
    if (t < nblocks) g_bsum[t] = s[t] - v;   // exclusive block offsets
}

__global__ void k_scan3() {
    int i = blockIdx.x * 1024 + threadIdx.x;
    if (i < NN) {
        int r = g_rowptr[i] + g_bsum[blockIdx.x];
        g_rowptr[i] = r;
        g_cursor[i] = r;
    }
    if (i == 0) g_rowptr[NN] = ET;
}

__global__ void k_fill(const int* __restrict__ ei) {
    int e = blockIdx.x * 256 + threadIdx.x;
    if (e < ET) {
        int d = edst_of(ei, e);
        int s = esrc_of(ei, e);
        int p = atomicAdd(&g_cursor[d], 1);
        g_esrc[p] = s;
    }
}

// ---------------- operand prep: fp32 -> bf16 hi/lo ----------------
__global__ void k_prep_x(const float* __restrict__ X) {
    int i = blockIdx.x * 256 + threadIdx.x;   // over NN*64/4 float4s
    if (i >= NN * 16) return;
    float4 v = ((const float4*)X)[i];
    __nv_bfloat16 hx = __float2bfloat16(v.x), hy = __float2bfloat16(v.y);
    __nv_bfloat16 hz = __float2bfloat16(v.z), hw = __float2bfloat16(v.w);
    __nv_bfloat16 lx = __float2bfloat16(v.x - __bfloat162float(hx));
    __nv_bfloat16 ly = __float2bfloat16(v.y - __bfloat162float(hy));
    __nv_bfloat16 lz = __float2bfloat16(v.z - __bfloat162float(hz));
    __nv_bfloat16 lw = __float2bfloat16(v.w - __bfloat162float(hw));
    uint2 hp = make_uint2(
        (uint32_t)__bfloat16_as_ushort(hx) | ((uint32_t)__bfloat16_as_ushort(hy) << 16),
        (uint32_t)__bfloat16_as_ushort(hz) | ((uint32_t)__bfloat16_as_ushort(hw) << 16));
    uint2 lp = make_uint2(
        (uint32_t)__bfloat16_as_ushort(lx) | ((uint32_t)__bfloat16_as_ushort(ly) << 16),
        (uint32_t)__bfloat16_as_ushort(lz) | ((uint32_t)__bfloat16_as_ushort(lw) << 16));
    ((uint2*)g_x_hi)[i] = hp;
    ((uint2*)g_x_lo)[i] = lp;
}

__global__ void k_prep_w1(const float* __restrict__ W1) {
    int idx = blockIdx.x * 256 + threadIdx.x;   // over 64*256
    if (idx >= 64 * D1) return;
    int k = idx / D1, n = idx % D1;
    float w = W1[idx];
    __nv_bfloat16 hi = __float2bfloat16(w);
    __nv_bfloat16 lo = __float2bfloat16(w - __bfloat162float(hi));
    g_wt1_hi[n * 64 + k] = hi;
    g_wt1_lo[n * 64 + k] = lo;
}
__global__ void k_prep_w2(const float* __restrict__ W2) {
    int idx = blockIdx.x * 256 + threadIdx.x;   // over 256*128
    if (idx >= D1 * D2) return;
    int k = idx / D2, n = idx % D2;
    float w = W2[idx];
    __nv_bfloat16 hi = __float2bfloat16(w);
    __nv_bfloat16 lo = __float2bfloat16(w - __bfloat162float(hi));
    g_wt2_hi[n * D1 + k] = hi;
    g_wt2_lo[n * D1 + k] = lo;
}

// ---------------- HMMA bf16 GEMM: hi/lo operands, cp.async double buffer ----------------
// C[M,NCOL] = (Ah+Al)(Bh+Bl)^T ~= Ah*Bh + Al*Bh + Ah*Bl. A:[M,KTOT], Bt:[NCOL,KTOT] bf16.
// Block 128x128, 8 warps (2x4) of 64x32. KC=32 chunks, 2-stage cp.async pipeline, ldmatrix.
#define KC 32
#define ASTR 40   // bf16 row stride: 80B. ldmatrix banks (r*20)%32 all-distinct -> conflict-free
#define TILE_ELEMS (128 * ASTR)

__device__ __forceinline__ void ldsm4(uint32_t& r0, uint32_t& r1, uint32_t& r2, uint32_t& r3,
                                      const __nv_bfloat16* p) {
    uint32_t a = (uint32_t)__cvta_generic_to_shared(p);
    asm volatile("ldmatrix.sync.aligned.m8n8.x4.shared.b16 {%0,%1,%2,%3}, [%4];"
                 : "=r"(r0), "=r"(r1), "=r"(r2), "=r"(r3) : "r"(a));
}
__device__ __forceinline__ void mma16816(float* d, uint32_t a0, uint32_t a1, uint32_t a2,
                                         uint32_t a3, uint32_t b0, uint32_t b1) {
    asm volatile(
        "mma.sync.aligned.m16n8k16.row.col.f32.bf16.bf16.f32 "
        "{%0,%1,%2,%3}, {%4,%5,%6,%7}, {%8,%9}, {%0,%1,%2,%3};"
        : "+f"(d[0]), "+f"(d[1]), "+f"(d[2]), "+f"(d[3])
        : "r"(a0), "r"(a1), "r"(a2), "r"(a3), "r"(b0), "r"(b1));
}
__device__ __forceinline__ void cpa16(__nv_bfloat16* dst, const __nv_bfloat16* src) {
    uint32_t d = (uint32_t)__cvta_generic_to_shared(dst);
    asm volatile("cp.async.cg.shared.global [%0], [%1], 16;" :: "r"(d), "l"(src));
}

template<int KTOT>
__global__ __launch_bounds__(256) void k_gemm_hl(const __nv_bfloat16* __restrict__ Ah,
                                                 const __nv_bfloat16* __restrict__ Al,
                                                 const __nv_bfloat16* __restrict__ Bh,
                                                 const __nv_bfloat16* __restrict__ Bl,
                                                 float* __restrict__ C,
                                                 int M, int NCOL) {
    constexpr int NCH = KTOT / KC;
    extern __shared__ __nv_bfloat16 sm[];

    int tid = threadIdx.x;
    int wid = tid >> 5, lane = tid & 31;
    int g = lane >> 2, tig = lane & 3;
    int wm = (wid >> 2) * 64;
    int wn = (wid & 3) * 32;
    int bm = blockIdx.y * 128;
    int bn = blockIdx.x * 128;

    float acc[4][4][4];
    #pragma unroll
    for (int mt = 0; mt < 4; mt++)
        #pragma unroll
        for (int nt = 0; nt < 4; nt++)
            #pragma unroll
            for (int f = 0; f < 4; f++) acc[mt][nt][f] = 0.f;

    // ldmatrix lane addressing (verified pattern from R4, which passed)
    int a_r = lane & 15, a_c = (lane >> 4) * 8;
    int b_r = (lane >> 4) * 8 + (lane & 7), b_c = ((lane >> 3) & 1) * 8;

    // fill indexing: 512 uint4 per tile, 2 per thread
    int frow0 = tid >> 2, fcol = (tid & 3) * 8;
    int frow1 = (tid + 256) >> 2;

    // issue fill for chunk c into stage s
    auto fill = [&](int s, int c) {
        __nv_bfloat16* s_ah = sm + (s * 4 + 0) * TILE_ELEMS;
        __nv_bfloat16* s_al = sm + (s * 4 + 1) * TILE_ELEMS;
        __nv_bfloat16* s_bh = sm + (s * 4 + 2) * TILE_ELEMS;
        __nv_bfloat16* s_bl = sm + (s * 4 + 3) * TILE_ELEMS;
        int kbase = c * KC;
        int ar0 = bm + frow0; if (ar0 >= M) ar0 = M - 1;   // rows>=M: garbage ok, discarded
        int ar1 = bm + frow1; if (ar1 >= M) ar1 = M - 1;
        size_t a0 = (size_t)ar0 * KTOT + kbase + fcol;
        size_t a1 = (size_t)ar1 * KTOT + kbase + fcol;
        size_t b0 = (size_t)(bn + frow0) * KTOT + kbase + fcol;
        size_t b1 = (size_t)(bn + frow1) * KTOT + kbase + fcol;
        cpa16(&s_ah[frow0 * ASTR + fcol], &Ah[a0]);
        cpa16(&s_ah[frow1 * ASTR + fcol], &Ah[a1]);
        cpa16(&s_al[frow0 * ASTR + fcol], &Al[a0]);
        cpa16(&s_al[frow1 * ASTR + fcol], &Al[a1]);
        cpa16(&s_bh[frow0 * ASTR + fcol], &Bh[b0]);
        cpa16(&s_bh[frow1 * ASTR + fcol], &Bh[b1]);
        cpa16(&s_bl[frow0 * ASTR + fcol], &Bl[b0]);
        cpa16(&s_bl[frow1 * ASTR + fcol], &Bl[b1]);
        asm volatile("cp.async.commit_group;");
    };

    fill(0, 0);
    int stage = 0;
    for (int c = 0; c < NCH; c++) {
        if (c + 1 < NCH) {
            fill(stage ^ 1, c + 1);
            asm volatile("cp.async.wait_group 1;");
        } else {
            asm volatile("cp.async.wait_group 0;");
        }
        __syncthreads();

        __nv_bfloat16* s_ah = sm + (stage * 4 + 0) * TILE_ELEMS;
        __nv_bfloat16* s_al = sm + (stage * 4 + 1) * TILE_ELEMS;
        __nv_bfloat16* s_bh = sm + (stage * 4 + 2) * TILE_ELEMS;
        __nv_bfloat16* s_bl = sm + (stage * 4 + 3) * TILE_ELEMS;

        #pragma unroll
        for (int ks = 0; ks < KC; ks += 16) {
            uint32_t bhf[4][2], blf[4][2];
            #pragma unroll
            for (int p = 0; p < 2; p++) {
                ldsm4(bhf[2*p][0], bhf[2*p][1], bhf[2*p+1][0], bhf[2*p+1][1],
                      &s_bh[(wn + p * 16 + b_r) * ASTR + ks + b_c]);
                ldsm4(blf[2*p][0], blf[2*p][1], blf[2*p+1][0], blf[2*p+1][1],
                      &s_bl[(wn + p * 16 + b_r) * ASTR + ks + b_c]);
            }
            #pragma unroll
            for (int mt = 0; mt < 4; mt++) {
                uint32_t ah0, ah1, ah2, ah3, al0, al1, al2, al3;
                ldsm4(ah0, ah1, ah2, ah3, &s_ah[(wm + mt * 16 + a_r) * ASTR + ks + a_c]);
                ldsm4(al0, al1, al2, al3, &s_al[(wm + mt * 16 + a_r) * ASTR + ks + a_c]);
                #pragma unroll
                for (int nt = 0; nt < 4; nt++)
                    mma16816(acc[mt][nt], ah0, ah1, ah2, ah3, bhf[nt][0], bhf[nt][1]);
                #pragma unroll
                for (int nt = 0; nt < 4; nt++)
                    mma16816(acc[mt][nt], al0, al1, al2, al3, bhf[nt][0], bhf[nt][1]);
                #pragma unroll
                for (int nt = 0; nt < 4; nt++)
                    mma16816(acc[mt][nt], ah0, ah1, ah2, ah3, blf[nt][0], blf[nt][1]);
            }
        }
        __syncthreads();
        stage ^= 1;
    }

    // epilogue: direct fp32 stores
    #pragma unroll
    for (int mt = 0; mt < 4; mt++) {
        int r0 = bm + wm + mt * 16 + g;
        int r1 = r0 + 8;
        #pragma unroll
        for (int nt = 0; nt < 4; nt++) {
            int col = bn + wn + nt * 8 + 2 * tig;
            if (r0 < M)
                *(float2*)&C[(size_t)r0 * NCOL + col] = make_float2(acc[mt][nt][0], acc[mt][nt][1]);
            if (r1 < M)
                *(float2*)&C[(size_t)r1 * NCOL + col] = make_float2(acc[mt][nt][2], acc[mt][nt][3]);
        }
    }
}

// ---------------- attention logit vectors ----------------
__global__ __launch_bounds__(256) void k_attn1(const float* __restrict__ att_s,
                                               const float* __restrict__ att_d) {
    int w = (blockIdx.x * blockDim.x + threadIdx.x) >> 5;
    int lane = threadIdx.x & 31;
    if (w >= NN) return;
    const float4* xp = (const float4*)&g_xh1[(size_t)w * D1 + lane * 8];
    float4 x0 = xp[0], x1 = xp[1];
    const float4* ap = (const float4*)&att_s[lane * 8];
    float4 a0 = ap[0], a1 = ap[1];
    const float4* dp = (const float4*)&att_d[lane * 8];
    float4 d0 = dp[0], d1 = dp[1];
    float ss = x0.x*a0.x + x0.y*a0.y + x0.z*a0.z + x0.w*a0.w
             + x1.x*a1.x + x1.y*a1.y + x1.z*a1.z + x1.w*a1.w;
    float sd = x0.x*d0.x + x0.y*d0.y + x0.z*d0.z + x0.w*d0.w
             + x1.x*d1.x + x1.y*d1.y + x1.z*d1.z + x1.w*d1.w;
    #pragma unroll
    for (int m = 1; m < 8; m <<= 1) {
        ss += __shfl_xor_sync(0xffffffffu, ss, m);
        sd += __shfl_xor_sync(0xffffffffu, sd, m);
    }
    if ((lane & 7) == 0) {
        int h = lane >> 3;
        g_as1[w * 4 + h] = ss;
        g_ad1[w * 4 + h] = sd;
    }
}

__global__ __launch_bounds__(256) void k_attn2(const float* __restrict__ att_s,
                                               const float* __restrict__ att_d) {
    int w = (blockIdx.x * blockDim.x + threadIdx.x) >> 5;
    int lane = threadIdx.x & 31;
    if (w >= NN) return;
    float4 x = *(const float4*)&g_xh2[(size_t)w * D2 + lane * 4];
    float4 a = *(const float4*)&att_s[lane * 4];
    float4 d = *(const float4*)&att_d[lane * 4];
    float ss = x.x*a.x + x.y*a.y + x.z*a.z + x.w*a.w;
    float sd = x.x*d.x + x.y*d.y + x.z*d.z + x.w*d.w;
    #pragma unroll
    for (int m = 1; m < 32; m <<= 1) {
        ss += __shfl_xor_sync(0xffffffffu, ss, m);
        sd += __shfl_xor_sync(0xffffffffu, sd, m);
    }
    if (lane == 0) { g_as2[w] = ss; g_ad2[w] = sd; }
}

// ---------------- layer-1 aggregation (computes+stores edge weights, emits bf16 hi/lo H1) ----
__global__ __launch_bounds__(256) void k_agg1(const float* __restrict__ bias) {
    int w = (blockIdx.x * blockDim.x + threadIdx.x) >> 5;
    int lane = threadIdx.x & 31;
    if (w >= NN) return;
    int start = g_rowptr[w], end = g_rowptr[w + 1];
    float4 ad = *(const float4*)&g_ad1[w * 4];

    // pass A: compute per-edge exp weights, store, accumulate denominators
    float s0 = 0.f, s1 = 0.f, s2 = 0.f, s3 = 0.f;
    for (int p = start + lane; p < end; p += 32) {
        int s = g_esrc[p];
        float4 as = *(const float4*)&g_as1[s * 4];
        float4 wv;
        wv.x = __expf(lrelu(as.x + ad.x));
        wv.y = __expf(lrelu(as.y + ad.y));
        wv.z = __expf(lrelu(as.z + ad.z));
        wv.w = __expf(lrelu(as.w + ad.w));
        *(float4*)&g_w1[p * 4] = wv;
        s0 += wv.x; s1 += wv.y; s2 += wv.z; s3 += wv.w;
    }
    #pragma unroll
    for (int m = 16; m >= 1; m >>= 1) {
        s0 += __shfl_xor_sync(0xffffffffu, s0, m);
        s1 += __shfl_xor_sync(0xffffffffu, s1, m);
        s2 += __shfl_xor_sync(0xffffffffu, s2, m);
        s3 += __shfl_xor_sync(0xffffffffu, s3, m);
    }

    int head = lane >> 3;
    float den = (head == 0) ? s0 : (head == 1) ? s1 : (head == 2) ? s2 : s3;
    float inv = 1.0f / den;

    // pass B: weighted gather, 2-edge unroll
    float acc0 = 0.f, acc1 = 0.f, acc2 = 0.f, acc3 = 0.f;
    float acc4 = 0.f, acc5 = 0.f, acc6 = 0.f, acc7 = 0.f;
    int p = start;
    for (; p + 1 < end; p += 2) {
        int sA = g_esrc[p];
        int sB = g_esrc[p + 1];
        float4 wA = *(const float4*)&g_w1[p * 4];
        float4 wB = *(const float4*)&g_w1[(p + 1) * 4];
        const float4* xa = (const float4*)&g_xh1[(size_t)sA * D1 + lane * 8];
        const float4* xb = (const float4*)&g_xh1[(size_t)sB * D1 + lane * 8];
        float4 a0 = xa[0], a1 = xa[1];
        float4 b0 = xb[0], b1 = xb[1];
        float gA = ((head == 0) ? wA.x : (head == 1) ? wA.y : (head == 2) ? wA.z : wA.w) * inv;
        float gB = ((head == 0) ? wB.x : (head == 1) ? wB.y : (head == 2) ? wB.z : wB.w) * inv;
        acc0 += gA * a0.x + gB * b0.x; acc1 += gA * a0.y + gB * b0.y;
        acc2 += gA * a0.z + gB * b0.z; acc3 += gA * a0.w + gB * b0.w;
        acc4 += gA * a1.x + gB * b1.x; acc5 += gA * a1.y + gB * b1.y;
        acc6 += gA * a1.z + gB * b1.z; acc7 += gA * a1.w + gB * b1.w;
    }
    if (p < end) {
        int sA = g_esrc[p];
        float4 wA = *(const float4*)&g_w1[p * 4];
        const float4* xa = (const float4*)&g_xh1[(size_t)sA * D1 + lane * 8];
        float4 a0 = xa[0], a1 = xa[1];
        float gA = ((head == 0) ? wA.x : (head == 1) ? wA.y : (head == 2) ? wA.z : wA.w) * inv;
        acc0 += gA * a0.x; acc1 += gA * a0.y; acc2 += gA * a0.z; acc3 += gA * a0.w;
        acc4 += gA * a1.x; acc5 += gA * a1.y; acc6 += gA * a1.z; acc7 += gA * a1.w;
    }
    const float4* bp = (const float4*)&bias[lane * 8];
    float4 b0 = bp[0], b1v = bp[1];
    float o[8] = { acc0 + b0.x, acc1 + b0.y, acc2 + b0.z, acc3 + b0.w,
                   acc4 + b1v.x, acc5 + b1v.y, acc6 + b1v.z, acc7 + b1v.w };
    // split to bf16 hi/lo and store (H1 kept only in hi/lo form)
    uint32_t hp[4], lp[4];
    #pragma unroll
    for (int j = 0; j < 4; j++) {
        __nv_bfloat16 h0 = __float2bfloat16(o[2*j]);
        __nv_bfloat16 h1 = __float2bfloat16(o[2*j+1]);
        __nv_bfloat16 l0 = __float2bfloat16(o[2*j]   - __bfloat162float(h0));
        __nv_bfloat16 l1 = __float2bfloat16(o[2*j+1] - __bfloat162float(h1));
        hp[j] = (uint32_t)__bfloat16_as_ushort(h0) | ((uint32_t)__bfloat16_as_ushort(h1) << 16);
        lp[j] = (uint32_t)__bfloat16_as_ushort(l0) | ((uint32_t)__bfloat16_as_ushort(l1) << 16);
    }
    *(uint4*)&g_h1_hi[(size_t)w * D1 + lane * 8] = make_uint4(hp[0], hp[1], hp[2], hp[3]);
    *(uint4*)&g_h1_lo[(size_t)w * D1 + lane * 8] = make_uint4(lp[0], lp[1], lp[2], lp[3]);
}

// ---------------- layer-2 aggregation (heads=1, C=128; computes+stores edge weights) ----
__global__ __launch_bounds__(256) void k_agg2(const float* __restrict__ bias,
                                              float* __restrict__ out) {
    int w = (blockIdx.x * blockDim.x + threadIdx.x) >> 5;
    int lane = threadIdx.x & 31;
    if (w >= NN) return;
    int start = g_rowptr[w], end = g_rowptr[w + 1];
    float ad = g_ad2[w];

    float se = 0.f;
    for (int p = start + lane; p < end; p += 32) {
        int s = g_esrc[p];
        float wv = __expf(lrelu(g_as2[s] + ad));
        g_w2[p] = wv;
        se += wv;
    }
    #pragma unroll
    for (int m = 16; m >= 1; m >>= 1)
        se += __shfl_xor_sync(0xffffffffu, se, m);
    float inv = 1.0f / se;

    float acc0 = 0.f, acc1 = 0.f, acc2 = 0.f, acc3 = 0.f;
    int p = start;
    for (; p + 1 < end; p += 2) {
        int sA = g_esrc[p];
        int sB = g_esrc[p + 1];
        float gA = g_w2[p] * inv;
        float gB = g_w2[p + 1] * inv;
        float4 va = *(const float4*)&g_xh2[(size_t)sA * D2 + lane * 4];
        float4 vb = *(const float4*)&g_xh2[(size_t)sB * D2 + lane * 4];
        acc0 += gA * va.x + gB * vb.x; acc1 += gA * va.y + gB * vb.y;
        acc2 += gA * va.z + gB * vb.z; acc3 += gA * va.w + gB * vb.w;
    }
    if (p < end) {
        int sA = g_esrc[p];
        float gA = g_w2[p] * inv;
        float4 va = *(const float4*)&g_xh2[(size_t)sA * D2 + lane * 4];
        acc0 += gA * va.x; acc1 += gA * va.y; acc2 += gA * va.z; acc3 += gA * va.w;
    }
    float4 b = *(const float4*)&bias[lane * 4];
    *(float4*)&out[(size_t)w * D2 + lane * 4] =
        make_float4(acc0 + b.x, acc1 + b.y, acc2 + b.z, acc3 + b.w);
}

// ---------------- host launch ----------------
extern "C" void kernel_launch(void* const* d_in, const int* in_sizes, int n_in,
                              void* d_out, int out_size) {
    const float* X    = (const float*)d_in[0];
    const int*   ei   = (const int*)  d_in[1];
    const float* W1   = (const float*)d_in[2];
    const float* as1  = (const float*)d_in[3];
    const float* ad1  = (const float*)d_in[4];
    const float* b1   = (const float*)d_in[5];
    const float* W2   = (const float*)d_in[6];
    const float* as2  = (const float*)d_in[7];
    const float* ad2  = (const float*)d_in[8];
    const float* b2   = (const float*)d_in[9];
    float* out = (float*)d_out;

    float *p_xh1, *p_xh2;
    cudaGetSymbolAddress((void**)&p_xh1, g_xh1);
    cudaGetSymbolAddress((void**)&p_xh2, g_xh2);
    __nv_bfloat16 *p_xh, *p_xl, *p_h1h, *p_h1l, *p_w1h, *p_w1l, *p_w2h, *p_w2l;
    cudaGetSymbolAddress((void**)&p_xh,  g_x_hi);
    cudaGetSymbolAddress((void**)&p_xl,  g_x_lo);
    cudaGetSymbolAddress((void**)&p_h1h, g_h1_hi);
    cudaGetSymbolAddress((void**)&p_h1l, g_h1_lo);
    cudaGetSymbolAddress((void**)&p_w1h, g_wt1_hi);
    cudaGetSymbolAddress((void**)&p_w1l, g_wt1_lo);
    cudaGetSymbolAddress((void**)&p_w2h, g_wt2_hi);
    cudaGetSymbolAddress((void**)&p_w2l, g_wt2_lo);

    const int SMEM_GEMM = 2 * 4 * TILE_ELEMS * 2;   // 81920 bytes
    cudaFuncSetAttribute(k_gemm_hl<64>,  cudaFuncAttributeMaxDynamicSharedMemorySize, SMEM_GEMM);
    cudaFuncSetAttribute(k_gemm_hl<256>, cudaFuncAttributeMaxDynamicSharedMemorySize, SMEM_GEMM);

    const int SCAN_BLOCKS = (NN + 1023) / 1024;   // 49
    const int NODE_BLOCKS = (NN + 7) / 8;
    const int M_BLOCKS = (NN + 127) / 128;        // 391
    const int EDGE_BLOCKS = (ET + 255) / 256;

    // slot 3 = layer-1 GEMM (ncu-profiled launch)
    k_zero_deg<<<(NN + 255) / 256, 256>>>();                                   // 0
    k_prep_x<<<(NN * 16 + 255) / 256, 256>>>(X);                               // 1
    k_prep_w1<<<(64 * D1 + 255) / 256, 256>>>(W1);                             // 2
    k_gemm_hl<64><<<dim3(D1 / 128, M_BLOCKS), 256, SMEM_GEMM>>>(p_xh, p_xl, p_w1h, p_w1l, p_xh1, NN, D1); // 3
    k_count<<<EDGE_BLOCKS, 256>>>(ei);                                         // 4
    k_scan1<<<SCAN_BLOCKS, 1024>>>();                                          // 5
    k_scan2<<<1, 64>>>(SCAN_BLOCKS);                                           // 6
    k_scan3<<<SCAN_BLOCKS, 1024>>>();                                          // 7
    k_fill<<<EDGE_BLOCKS, 256>>>(ei);                                          // 8
    k_attn1<<<NODE_BLOCKS, 256>>>(as1, ad1);                                   // 9
    k_agg1<<<NODE_BLOCKS, 256>>>(b1);                                          // 10
    k_prep_w2<<<(D1 * D2 + 255) / 256, 256>>>(W2);                             // 11
    k_gemm_hl<256><<<dim3(D2 / 128, M_BLOCKS), 256, SMEM_GEMM>>>(p_h1h, p_h1l, p_w2h, p_w2l, p_xh2, NN, D2); // 12
    k_attn2<<<NODE_BLOCKS, 256>>>(as2, ad2);                                   // 13
    k_agg2<<<NODE_BLOCKS, 256>>>(b2, out);                                     // 14
}

// round 8
// speedup vs baseline: 1.8943x; 1.0824x over previous
#include <cuda_runtime.h>
#include <cuda_bf16.h>
#include <cstdint>

#define NN 50000
#define NE 800000
#define ET 850000   // NE + NN self loops
#define D1 256      // heads(4) * h1(64)
#define D2 128

// ---------------- device scratch (static; no runtime allocation) ----------------
__device__ __align__(16) float g_xh1[NN * D1];   // X @ W1 (fp32, for attn1 + agg1 gather)
__device__ __align__(16) float g_xh2[NN * D2];   // H1 @ W2 (fp32, for attn2 + agg2 gather)
__device__ __align__(16) __nv_bfloat16 g_x_hi[NN * 64];   // X split
__device__ __align__(16) __nv_bfloat16 g_x_lo[NN * 64];
__device__ __align__(16) __nv_bfloat16 g_h1_hi[NN * D1];  // H1 split (gemm2 A operand)
__device__ __align__(16) __nv_bfloat16 g_h1_lo[NN * D1];
__device__ __align__(16) float g_as1[NN * 4];
__device__ __align__(16) float g_ad1[NN * 4];
__device__ float g_as2[NN];
__device__ float g_ad2[NN];
__device__ int g_deg[NN];
__device__ int g_rowptr[NN + 1];
__device__ int g_rank[ET];      // edge -> within-destination rank (from count atomic)
__device__ int g_esrc[ET];      // CSR-position -> source node
__device__ int g_bsum[64];
// transposed bf16 hi/lo weights: Wt[n][k]
__device__ __align__(16) __nv_bfloat16 g_wt1_hi[D1 * 64];
__device__ __align__(16) __nv_bfloat16 g_wt1_lo[D1 * 64];
__device__ __align__(16) __nv_bfloat16 g_wt2_hi[D2 * D1];
__device__ __align__(16) __nv_bfloat16 g_wt2_lo[D2 * D1];

__device__ __forceinline__ int esrc_of(const int* __restrict__ ei, int e) {
    return e < NE ? ei[e] : e - NE;
}
__device__ __forceinline__ int edst_of(const int* __restrict__ ei, int e) {
    return e < NE ? ei[NE + e] : e - NE;
}
__device__ __forceinline__ float lrelu(float x) { return x > 0.f ? x : 0.2f * x; }

// ---------------- CSR build ----------------
__global__ void k_zero_deg() {
    int i = blockIdx.x * 256 + threadIdx.x;
    if (i < NN) g_deg[i] = 0;
}

__global__ void k_count(const int* __restrict__ ei) {
    int e = blockIdx.x * 256 + threadIdx.x;
    if (e < ET) {
        int r = atomicAdd(&g_deg[edst_of(ei, e)], 1);
        g_rank[e] = r;
    }
}

__global__ void k_scan1() {
    __shared__ int s[1024];
    int t = threadIdx.x;
    int i = blockIdx.x * 1024 + t;
    int v = (i < NN) ? g_deg[i] : 0;
    s[t] = v;
    __syncthreads();
    #pragma unroll
    for (int off = 1; off < 1024; off <<= 1) {
        int x = (t >= off) ? s[t - off] : 0;
        __syncthreads();
        s[t] += x;
        __syncthreads();
    }
    if (i < NN) g_rowptr[i] = s[t] - v;   // exclusive
    if (t == 1023) g_bsum[blockIdx.x] = s[t];
}

__global__ void k_scan2(int nblocks) {
    __shared__ int s[64];
    int t = threadIdx.x;
    int v = (t < nblocks) ? g_bsum[t] : 0;
    s[t] = v;
    __syncthreads();
    #pragma unroll
    for (int off = 1; off < 64; off <<= 1) {
        int x = (t >= off) ? s[t - off] : 0;
        __syncthreads();
        s[t] += x;
        __syncthreads();
    }
    if (t < nblocks) g_bsum[t] = s[t] - v;   // exclusive block offsets
}

__global__ void k_scan3() {
    int i = blockIdx.x * 1024 + threadIdx.x;
    if (i < NN)
        g_rowptr[i] = g_rowptr[i] + g_bsum[blockIdx.x];
    if (i == 0) g_rowptr[NN] = ET;
}

__global__ void k_fill(const int* __restrict__ ei) {
    int e = blockIdx.x * 256 + threadIdx.x;
    if (e < ET) {
        int d = edst_of(ei, e);
        int s = esrc_of(ei, e);
        g_esrc[g_rowptr[d] + g_rank[e]] = s;
    }
}

// ---------------- operand prep: fp32 -> bf16 hi/lo ----------------
__global__ void k_prep_x(const float* __restrict__ X) {
    int i = blockIdx.x * 256 + threadIdx.x;   // over NN*64/4 float4s
    if (i >= NN * 16) return;
    float4 v = ((const float4*)X)[i];
    __nv_bfloat16 hx = __float2bfloat16(v.x), hy = __float2bfloat16(v.y);
    __nv_bfloat16 hz = __float2bfloat16(v.z), hw = __float2bfloat16(v.w);
    __nv_bfloat16 lx = __float2bfloat16(v.x - __bfloat162float(hx));
    __nv_bfloat16 ly = __float2bfloat16(v.y - __bfloat162float(hy));
    __nv_bfloat16 lz = __float2bfloat16(v.z - __bfloat162float(hz));
    __nv_bfloat16 lw = __float2bfloat16(v.w - __bfloat162float(hw));
    uint2 hp = make_uint2(
        (uint32_t)__bfloat16_as_ushort(hx) | ((uint32_t)__bfloat16_as_ushort(hy) << 16),
        (uint32_t)__bfloat16_as_ushort(hz) | ((uint32_t)__bfloat16_as_ushort(hw) << 16));
    uint2 lp = make_uint2(
        (uint32_t)__bfloat16_as_ushort(lx) | ((uint32_t)__bfloat16_as_ushort(ly) << 16),
        (uint32_t)__bfloat16_as_ushort(lz) | ((uint32_t)__bfloat16_as_ushort(lw) << 16));
    ((uint2*)g_x_hi)[i] = hp;
    ((uint2*)g_x_lo)[i] = lp;
}

__global__ void k_prep_w1(const float* __restrict__ W1) {
    int idx = blockIdx.x * 256 + threadIdx.x;   // over 64*256
    if (idx >= 64 * D1) return;
    int k = idx / D1, n = idx % D1;
    float w = W1[idx];
    __nv_bfloat16 hi = __float2bfloat16(w);
    __nv_bfloat16 lo = __float2bfloat16(w - __bfloat162float(hi));
    g_wt1_hi[n * 64 + k] = hi;
    g_wt1_lo[n * 64 + k] = lo;
}
__global__ void k_prep_w2(const float* __restrict__ W2) {
    int idx = blockIdx.x * 256 + threadIdx.x;   // over 256*128
    if (idx >= D1 * D2) return;
    int k = idx / D2, n = idx % D2;
    float w = W2[idx];
    __nv_bfloat16 hi = __float2bfloat16(w);
    __nv_bfloat16 lo = __float2bfloat16(w - __bfloat162float(hi));
    g_wt2_hi[n * D1 + k] = hi;
    g_wt2_lo[n * D1 + k] = lo;
}

// ---------------- HMMA bf16 GEMM: hi/lo operands, cp.async double buffer ----------------
#define KC 32
#define ASTR 40
#define TILE_ELEMS (128 * ASTR)

__device__ __forceinline__ void ldsm4(uint32_t& r0, uint32_t& r1, uint32_t& r2, uint32_t& r3,
                                      const __nv_bfloat16* p) {
    uint32_t a = (uint32_t)__cvta_generic_to_shared(p);
    asm volatile("ldmatrix.sync.aligned.m8n8.x4.shared.b16 {%0,%1,%2,%3}, [%4];"
                 : "=r"(r0), "=r"(r1), "=r"(r2), "=r"(r3) : "r"(a));
}
__device__ __forceinline__ void mma16816(float* d, uint32_t a0, uint32_t a1, uint32_t a2,
                                         uint32_t a3, uint32_t b0, uint32_t b1) {
    asm volatile(
        "mma.sync.aligned.m16n8k16.row.col.f32.bf16.bf16.f32 "
        "{%0,%1,%2,%3}, {%4,%5,%6,%7}, {%8,%9}, {%0,%1,%2,%3};"
        : "+f"(d[0]), "+f"(d[1]), "+f"(d[2]), "+f"(d[3])
        : "r"(a0), "r"(a1), "r"(a2), "r"(a3), "r"(b0), "r"(b1));
}
__device__ __forceinline__ void cpa16(__nv_bfloat16* dst, const __nv_bfloat16* src) {
    uint32_t d = (uint32_t)__cvta_generic_to_shared(dst);
    asm volatile("cp.async.cg.shared.global [%0], [%1], 16;" :: "r"(d), "l"(src));
}

template<int KTOT>
__global__ __launch_bounds__(256) void k_gemm_hl(const __nv_bfloat16* __restrict__ Ah,
                                                 const __nv_bfloat16* __restrict__ Al,
                                                 const __nv_bfloat16* __restrict__ Bh,
                                                 const __nv_bfloat16* __restrict__ Bl,
                                                 float* __restrict__ C,
                                                 int M, int NCOL) {
    constexpr int NCH = KTOT / KC;
    extern __shared__ __nv_bfloat16 sm[];

    int tid = threadIdx.x;
    int wid = tid >> 5, lane = tid & 31;
    int g = lane >> 2, tig = lane & 3;
    int wm = (wid >> 2) * 64;
    int wn = (wid & 3) * 32;
    int bm = blockIdx.y * 128;
    int bn = blockIdx.x * 128;

    float acc[4][4][4];
    #pragma unroll
    for (int mt = 0; mt < 4; mt++)
        #pragma unroll
        for (int nt = 0; nt < 4; nt++)
            #pragma unroll
            for (int f = 0; f < 4; f++) acc[mt][nt][f] = 0.f;

    int a_r = lane & 15, a_c = (lane >> 4) * 8;
    int b_r = (lane >> 4) * 8 + (lane & 7), b_c = ((lane >> 3) & 1) * 8;

    int frow0 = tid >> 2, fcol = (tid & 3) * 8;
    int frow1 = (tid + 256) >> 2;

    auto fill = [&](int s, int c) {
        __nv_bfloat16* s_ah = sm + (s * 4 + 0) * TILE_ELEMS;
        __nv_bfloat16* s_al = sm + (s * 4 + 1) * TILE_ELEMS;
        __nv_bfloat16* s_bh = sm + (s * 4 + 2) * TILE_ELEMS;
        __nv_bfloat16* s_bl = sm + (s * 4 + 3) * TILE_ELEMS;
        int kbase = c * KC;
        int ar0 = bm + frow0; if (ar0 >= M) ar0 = M - 1;
        int ar1 = bm + frow1; if (ar1 >= M) ar1 = M - 1;
        size_t a0 = (size_t)ar0 * KTOT + kbase + fcol;
        size_t a1 = (size_t)ar1 * KTOT + kbase + fcol;
        size_t b0 = (size_t)(bn + frow0) * KTOT + kbase + fcol;
        size_t b1 = (size_t)(bn + frow1) * KTOT + kbase + fcol;
        cpa16(&s_ah[frow0 * ASTR + fcol], &Ah[a0]);
        cpa16(&s_ah[frow1 * ASTR + fcol], &Ah[a1]);
        cpa16(&s_al[frow0 * ASTR + fcol], &Al[a0]);
        cpa16(&s_al[frow1 * ASTR + fcol], &Al[a1]);
        cpa16(&s_bh[frow0 * ASTR + fcol], &Bh[b0]);
        cpa16(&s_bh[frow1 * ASTR + fcol], &Bh[b1]);
        cpa16(&s_bl[frow0 * ASTR + fcol], &Bl[b0]);
        cpa16(&s_bl[frow1 * ASTR + fcol], &Bl[b1]);
        asm volatile("cp.async.commit_group;");
    };

    fill(0, 0);
    int stage = 0;
    for (int c = 0; c < NCH; c++) {
        if (c + 1 < NCH) {
            fill(stage ^ 1, c + 1);
            asm volatile("cp.async.wait_group 1;");
        } else {
            asm volatile("cp.async.wait_group 0;");
        }
        __syncthreads();

        __nv_bfloat16* s_ah = sm + (stage * 4 + 0) * TILE_ELEMS;
        __nv_bfloat16* s_al = sm + (stage * 4 + 1) * TILE_ELEMS;
        __nv_bfloat16* s_bh = sm + (stage * 4 + 2) * TILE_ELEMS;
        __nv_bfloat16* s_bl = sm + (stage * 4 + 3) * TILE_ELEMS;

        #pragma unroll
        for (int ks = 0; ks < KC; ks += 16) {
            uint32_t bhf[4][2], blf[4][2];
            #pragma unroll
            for (int p = 0; p < 2; p++) {
                ldsm4(bhf[2*p][0], bhf[2*p][1], bhf[2*p+1][0], bhf[2*p+1][1],
                      &s_bh[(wn + p * 16 + b_r) * ASTR + ks + b_c]);
                ldsm4(blf[2*p][0], blf[2*p][1], blf[2*p+1][0], blf[2*p+1][1],
                      &s_bl[(wn + p * 16 + b_r) * ASTR + ks + b_c]);
            }
            #pragma unroll
            for (int mt = 0; mt < 4; mt++) {
                uint32_t ah0, ah1, ah2, ah3, al0, al1, al2, al3;
                ldsm4(ah0, ah1, ah2, ah3, &s_ah[(wm + mt * 16 + a_r) * ASTR + ks + a_c]);
                ldsm4(al0, al1, al2, al3, &s_al[(wm + mt * 16 + a_r) * ASTR + ks + a_c]);
                #pragma unroll
                for (int nt = 0; nt < 4; nt++)
                    mma16816(acc[mt][nt], ah0, ah1, ah2, ah3, bhf[nt][0], bhf[nt][1]);
                #pragma unroll
                for (int nt = 0; nt < 4; nt++)
                    mma16816(acc[mt][nt], al0, al1, al2, al3, bhf[nt][0], bhf[nt][1]);
                #pragma unroll
                for (int nt = 0; nt < 4; nt++)
                    mma16816(acc[mt][nt], ah0, ah1, ah2, ah3, blf[nt][0], blf[nt][1]);
            }
        }
        __syncthreads();
        stage ^= 1;
    }

    #pragma unroll
    for (int mt = 0; mt < 4; mt++) {
        int r0 = bm + wm + mt * 16 + g;
        int r1 = r0 + 8;
        #pragma unroll
        for (int nt = 0; nt < 4; nt++) {
            int col = bn + wn + nt * 8 + 2 * tig;
            if (r0 < M)
                *(float2*)&C[(size_t)r0 * NCOL + col] = make_float2(acc[mt][nt][0], acc[mt][nt][1]);
            if (r1 < M)
                *(float2*)&C[(size_t)r1 * NCOL + col] = make_float2(acc[mt][nt][2], acc[mt][nt][3]);
        }
    }
}

// ---------------- attention logit vectors ----------------
__global__ __launch_bounds__(256) void k_attn1(const float* __restrict__ att_s,
                                               const float* __restrict__ att_d) {
    int w = (blockIdx.x * blockDim.x + threadIdx.x) >> 5;
    int lane = threadIdx.x & 31;
    if (w >= NN) return;
    const float4* xp = (const float4*)&g_xh1[(size_t)w * D1 + lane * 8];
    float4 x0 = xp[0], x1 = xp[1];
    const float4* ap = (const float4*)&att_s[lane * 8];
    float4 a0 = ap[0], a1 = ap[1];
    const float4* dp = (const float4*)&att_d[lane * 8];
    float4 d0 = dp[0], d1 = dp[1];
    float ss = x0.x*a0.x + x0.y*a0.y + x0.z*a0.z + x0.w*a0.w
             + x1.x*a1.x + x1.y*a1.y + x1.z*a1.z + x1.w*a1.w;
    float sd = x0.x*d0.x + x0.y*d0.y + x0.z*d0.z + x0.w*d0.w
             + x1.x*d1.x + x1.y*d1.y + x1.z*d1.z + x1.w*d1.w;
    #pragma unroll
    for (int m = 1; m < 8; m <<= 1) {
        ss += __shfl_xor_sync(0xffffffffu, ss, m);
        sd += __shfl_xor_sync(0xffffffffu, sd, m);
    }
    if ((lane & 7) == 0) {
        int h = lane >> 3;
        g_as1[w * 4 + h] = ss;
        g_ad1[w * 4 + h] = sd;
    }
}

__global__ __launch_bounds__(256) void k_attn2(const float* __restrict__ att_s,
                                               const float* __restrict__ att_d) {
    int w = (blockIdx.x * blockDim.x + threadIdx.x) >> 5;
    int lane = threadIdx.x & 31;
    if (w >= NN) return;
    float4 x = *(const float4*)&g_xh2[(size_t)w * D2 + lane * 4];
    float4 a = *(const float4*)&att_s[lane * 4];
    float4 d = *(const float4*)&att_d[lane * 4];
    float ss = x.x*a.x + x.y*a.y + x.z*a.z + x.w*a.w;
    float sd = x.x*d.x + x.y*d.y + x.z*d.z + x.w*d.w;
    #pragma unroll
    for (int m = 1; m < 32; m <<= 1) {
        ss += __shfl_xor_sync(0xffffffffu, ss, m);
        sd += __shfl_xor_sync(0xffffffffu, sd, m);
    }
    if (lane == 0) { g_as2[w] = ss; g_ad2[w] = sd; }
}

// ---------------- layer-1 aggregation: single pass, post-divide softmax ----------------
// out = (sum_e w_e * x_e) / (sum_e w_e). Each lane: head = lane>>3, 8 channels.
__global__ __launch_bounds__(256) void k_agg1(const float* __restrict__ bias) {
    int w = (blockIdx.x * blockDim.x + threadIdx.x) >> 5;
    int lane = threadIdx.x & 31;
    if (w >= NN) return;
    int start = g_rowptr[w], end = g_rowptr[w + 1];
    int head = lane >> 3;
    float4 ad4 = *(const float4*)&g_ad1[w * 4];
    float adh = (head == 0) ? ad4.x : (head == 1) ? ad4.y : (head == 2) ? ad4.z : ad4.w;

    float den = 0.f;
    float acc0 = 0.f, acc1 = 0.f, acc2 = 0.f, acc3 = 0.f;
    float acc4 = 0.f, acc5 = 0.f, acc6 = 0.f, acc7 = 0.f;
    int p = start;
    for (; p + 1 < end; p += 2) {
        int sA = g_esrc[p];
        int sB = g_esrc[p + 1];
        float lA = g_as1[sA * 4 + head];
        float lB = g_as1[sB * 4 + head];
        const float4* xa = (const float4*)&g_xh1[(size_t)sA * D1 + lane * 8];
        const float4* xb = (const float4*)&g_xh1[(size_t)sB * D1 + lane * 8];
        float4 a0 = xa[0], a1 = xa[1];
        float4 b0 = xb[0], b1 = xb[1];
        float gA = __expf(lrelu(lA + adh));
        float gB = __expf(lrelu(lB + adh));
        den += gA + gB;
        acc0 += gA * a0.x + gB * b0.x; acc1 += gA * a0.y + gB * b0.y;
        acc2 += gA * a0.z + gB * b0.z; acc3 += gA * a0.w + gB * b0.w;
        acc4 += gA * a1.x + gB * b1.x; acc5 += gA * a1.y + gB * b1.y;
        acc6 += gA * a1.z + gB * b1.z; acc7 += gA * a1.w + gB * b1.w;
    }
    if (p < end) {
        int sA = g_esrc[p];
        float gA = __expf(lrelu(g_as1[sA * 4 + head] + adh));
        const float4* xa = (const float4*)&g_xh1[(size_t)sA * D1 + lane * 8];
        float4 a0 = xa[0], a1 = xa[1];
        den += gA;
        acc0 += gA * a0.x; acc1 += gA * a0.y; acc2 += gA * a0.z; acc3 += gA * a0.w;
        acc4 += gA * a1.x; acc5 += gA * a1.y; acc6 += gA * a1.z; acc7 += gA * a1.w;
    }
    float inv = 1.0f / den;
    const float4* bp = (const float4*)&bias[lane * 8];
    float4 b0 = bp[0], b1v = bp[1];
    float o[8] = { acc0 * inv + b0.x,  acc1 * inv + b0.y,
                   acc2 * inv + b0.z,  acc3 * inv + b0.w,
                   acc4 * inv + b1v.x, acc5 * inv + b1v.y,
                   acc6 * inv + b1v.z, acc7 * inv + b1v.w };
    uint32_t hp[4], lp[4];
    #pragma unroll
    for (int j = 0; j < 4; j++) {
        __nv_bfloat16 h0 = __float2bfloat16(o[2*j]);
        __nv_bfloat16 h1 = __float2bfloat16(o[2*j+1]);
        __nv_bfloat16 l0 = __float2bfloat16(o[2*j]   - __bfloat162float(h0));
        __nv_bfloat16 l1 = __float2bfloat16(o[2*j+1] - __bfloat162float(h1));
        hp[j] = (uint32_t)__bfloat16_as_ushort(h0) | ((uint32_t)__bfloat16_as_ushort(h1) << 16);
        lp[j] = (uint32_t)__bfloat16_as_ushort(l0) | ((uint32_t)__bfloat16_as_ushort(l1) << 16);
    }
    *(uint4*)&g_h1_hi[(size_t)w * D1 + lane * 8] = make_uint4(hp[0], hp[1], hp[2], hp[3]);
    *(uint4*)&g_h1_lo[(size_t)w * D1 + lane * 8] = make_uint4(lp[0], lp[1], lp[2], lp[3]);
}

// ---------------- layer-2 aggregation: single pass, post-divide softmax ----------------
__global__ __launch_bounds__(256) void k_agg2(const float* __restrict__ bias,
                                              float* __restrict__ out) {
    int w = (blockIdx.x * blockDim.x + threadIdx.x) >> 5;
    int lane = threadIdx.x & 31;
    if (w >= NN) return;
    int start = g_rowptr[w], end = g_rowptr[w + 1];
    float ad = g_ad2[w];

    float den = 0.f;
    float acc0 = 0.f, acc1 = 0.f, acc2 = 0.f, acc3 = 0.f;
    int p = start;
    for (; p + 1 < end; p += 2) {
        int sA = g_esrc[p];
        int sB = g_esrc[p + 1];
        float lA = g_as2[sA];
        float lB = g_as2[sB];
        float4 va = *(const float4*)&g_xh2[(size_t)sA * D2 + lane * 4];
        float4 vb = *(const float4*)&g_xh2[(size_t)sB * D2 + lane * 4];
        float gA = __expf(lrelu(lA + ad));
        float gB = __expf(lrelu(lB + ad));
        den += gA + gB;
        acc0 += gA * va.x + gB * vb.x; acc1 += gA * va.y + gB * vb.y;
        acc2 += gA * va.z + gB * vb.z; acc3 += gA * va.w + gB * vb.w;
    }
    if (p < end) {
        int sA = g_esrc[p];
        float gA = __expf(lrelu(g_as2[sA] + ad));
        float4 va = *(const float4*)&g_xh2[(size_t)sA * D2 + lane * 4];
        den += gA;
        acc0 += gA * va.x; acc1 += gA * va.y; acc2 += gA * va.z; acc3 += gA * va.w;
    }
    float inv = 1.0f / den;
    float4 b = *(const float4*)&bias[lane * 4];
    *(float4*)&out[(size_t)w * D2 + lane * 4] =
        make_float4(acc0 * inv + b.x, acc1 * inv + b.y, acc2 * inv + b.z, acc3 * inv + b.w);
}

// ---------------- host launch ----------------
extern "C" void kernel_launch(void* const* d_in, const int* in_sizes, int n_in,
                              void* d_out, int out_size) {
    const float* X    = (const float*)d_in[0];
    const int*   ei   = (const int*)  d_in[1];
    const float* W1   = (const float*)d_in[2];
    const float* as1  = (const float*)d_in[3];
    const float* ad1  = (const float*)d_in[4];
    const float* b1   = (const float*)d_in[5];
    const float* W2   = (const float*)d_in[6];
    const float* as2  = (const float*)d_in[7];
    const float* ad2  = (const float*)d_in[8];
    const float* b2   = (const float*)d_in[9];
    float* out = (float*)d_out;

    float *p_xh1, *p_xh2;
    cudaGetSymbolAddress((void**)&p_xh1, g_xh1);
    cudaGetSymbolAddress((void**)&p_xh2, g_xh2);
    __nv_bfloat16 *p_xh, *p_xl, *p_h1h, *p_h1l, *p_w1h, *p_w1l, *p_w2h, *p_w2l;
    cudaGetSymbolAddress((void**)&p_xh,  g_x_hi);
    cudaGetSymbolAddress((void**)&p_xl,  g_x_lo);
    cudaGetSymbolAddress((void**)&p_h1h, g_h1_hi);
    cudaGetSymbolAddress((void**)&p_h1l, g_h1_lo);
    cudaGetSymbolAddress((void**)&p_w1h, g_wt1_hi);
    cudaGetSymbolAddress((void**)&p_w1l, g_wt1_lo);
    cudaGetSymbolAddress((void**)&p_w2h, g_wt2_hi);
    cudaGetSymbolAddress((void**)&p_w2l, g_wt2_lo);

    const int SMEM_GEMM = 2 * 4 * TILE_ELEMS * 2;   // 81920 bytes
    cudaFuncSetAttribute(k_gemm_hl<64>,  cudaFuncAttributeMaxDynamicSharedMemorySize, SMEM_GEMM);
    cudaFuncSetAttribute(k_gemm_hl<256>, cudaFuncAttributeMaxDynamicSharedMemorySize, SMEM_GEMM);

    const int SCAN_BLOCKS = (NN + 1023) / 1024;   // 49
    const int NODE_BLOCKS = (NN + 7) / 8;
    const int M_BLOCKS = (NN + 127) / 128;        // 391
    const int EDGE_BLOCKS = (ET + 255) / 256;

    // slot 3 = layer-1 GEMM (ncu-profiled launch)
    k_zero_deg<<<(NN + 255) / 256, 256>>>();                                   // 0
    k_prep_x<<<(NN * 16 + 255) / 256, 256>>>(X);                               // 1
    k_prep_w1<<<(64 * D1 + 255) / 256, 256>>>(W1);                             // 2
    k_gemm_hl<64><<<dim3(D1 / 128, M_BLOCKS), 256, SMEM_GEMM>>>(p_xh, p_xl, p_w1h, p_w1l, p_xh1, NN, D1); // 3
    k_count<<<EDGE_BLOCKS, 256>>>(ei);                                         // 4
    k_scan1<<<SCAN_BLOCKS, 1024>>>();                                          // 5
    k_scan2<<<1, 64>>>(SCAN_BLOCKS);                                           // 6
    k_scan3<<<SCAN_BLOCKS, 1024>>>();                                          // 7
    k_fill<<<EDGE_BLOCKS, 256>>>(ei);                                          // 8
    k_attn1<<<NODE_BLOCKS, 256>>>(as1, ad1);                                   // 9
    k_agg1<<<NODE_BLOCKS, 256>>>(b1);                                          // 10
    k_prep_w2<<<(D1 * D2 + 255) / 256, 256>>>(W2);                             // 11
    k_gemm_hl<256><<<dim3(D2 / 128, M_BLOCKS), 256, SMEM_GEMM>>>(p_h1h, p_h1l, p_w2h, p_w2l, p_xh2, NN, D2); // 12
    k_attn2<<<NODE_BLOCKS, 256>>>(as2, ad2);                                   // 13
    k_agg2<<<NODE_BLOCKS, 256>>>(b2, out);                                     // 14
}